// round 2
// baseline (speedup 1.0000x reference)
#include <cuda_runtime.h>
#include <math.h>

#define NL 2
#define NB 64
#define NT 256
#define NI 512
#define NH 1024
#define NO 256
#define G4 (4*NH)   // 4096

// ---------------- scratch (device globals; no allocation allowed) ----------------
__device__ __align__(16) float g_pre0[NT*NB*G4];        // [t][b][4H]  (~268 MB)
__device__ __align__(16) float g_hbuf[NL][2][NB*NH];    // ping-pong h state per layer
__device__ __align__(16) float g_c[NL][NB*NH];          // c state (block-owned, in place)
__device__ __align__(16) float g_h0out[NB*NH];          // masked layer0 output (layer1 input)
__device__ __align__(16) float g_lstm_out[NB*NT*NH];    // [b][t][H]
__device__ __align__(16) float g_fc1[NB*NT*NH];

// ---------------- helpers ----------------
__device__ __forceinline__ void fma16(float (&acc)[4][4], float4 av, float4 wv) {
    acc[0][0] = fmaf(av.x, wv.x, acc[0][0]);
    acc[0][1] = fmaf(av.x, wv.y, acc[0][1]);
    acc[0][2] = fmaf(av.x, wv.z, acc[0][2]);
    acc[0][3] = fmaf(av.x, wv.w, acc[0][3]);
    acc[1][0] = fmaf(av.y, wv.x, acc[1][0]);
    acc[1][1] = fmaf(av.y, wv.y, acc[1][1]);
    acc[1][2] = fmaf(av.y, wv.z, acc[1][2]);
    acc[1][3] = fmaf(av.y, wv.w, acc[1][3]);
    acc[2][0] = fmaf(av.z, wv.x, acc[2][0]);
    acc[2][1] = fmaf(av.z, wv.y, acc[2][1]);
    acc[2][2] = fmaf(av.z, wv.z, acc[2][2]);
    acc[2][3] = fmaf(av.z, wv.w, acc[2][3]);
    acc[3][0] = fmaf(av.w, wv.x, acc[3][0]);
    acc[3][1] = fmaf(av.w, wv.y, acc[3][1]);
    acc[3][2] = fmaf(av.w, wv.z, acc[3][2]);
    acc[3][3] = fmaf(av.w, wv.w, acc[3][3]);
}

__device__ __forceinline__ float sigmoidf_(float x) { return 1.f / (1.f + expf(-x)); }

// ---------------- init: weighted hidden + cell copy ----------------
__global__ void init_state_kernel(const float* __restrict__ clstm,
                                  const float* __restrict__ hidden,
                                  const float* __restrict__ cell,
                                  const int* __restrict__ lens)
{
    int l = blockIdx.x >> 6;       // / NB
    int b = blockIdx.x & 63;
    const float* cl = clstm + (size_t)b * NH;
    const float* hd = hidden + ((size_t)l * NB + b) * NH;
    const float* ce = cell   + ((size_t)l * NB + b) * NH;

    float cmn = 3.4e38f, cmx = -3.4e38f, hmn = 3.4e38f, hmx = -3.4e38f;
    for (int h = threadIdx.x; h < NH; h += 256) {
        float cv = cl[h], hv = hd[h];
        cmn = fminf(cmn, cv); cmx = fmaxf(cmx, cv);
        hmn = fminf(hmn, hv); hmx = fmaxf(hmx, hv);
    }
#pragma unroll
    for (int o = 16; o; o >>= 1) {
        cmn = fminf(cmn, __shfl_xor_sync(0xffffffffu, cmn, o));
        cmx = fmaxf(cmx, __shfl_xor_sync(0xffffffffu, cmx, o));
        hmn = fminf(hmn, __shfl_xor_sync(0xffffffffu, hmn, o));
        hmx = fmaxf(hmx, __shfl_xor_sync(0xffffffffu, hmx, o));
    }
    __shared__ float s[4][8];
    __shared__ float fs[4];
    int w = threadIdx.x >> 5, ln = threadIdx.x & 31;
    if (ln == 0) { s[0][w] = cmn; s[1][w] = cmx; s[2][w] = hmn; s[3][w] = hmx; }
    __syncthreads();
    if (threadIdx.x < 4) {
        float v = s[threadIdx.x][0];
        bool ismin = (threadIdx.x == 0) || (threadIdx.x == 2);
#pragma unroll
        for (int i = 1; i < 8; i++) {
            float x = s[threadIdx.x][i];
            v = ismin ? fminf(v, x) : fmaxf(v, x);
        }
        fs[threadIdx.x] = v;
    }
    __syncthreads();
    cmn = fs[0]; cmx = fs[1]; hmn = fs[2]; hmx = fs[3];
    float crange = cmx - cmn, hrange = hmx - hmn;
    bool lz = (lens[b] == 0);

    float* hout = g_hbuf[l][0] + (size_t)b * NH;
    float* cout = g_c[l]       + (size_t)b * NH;
    for (int h = threadIdx.x; h < NH; h += 256) {
        float cv = cl[h], hv = hd[h];
        float s1 = (crange > 0.f) ? (cv - cmn) / crange : cv;
        float s2 = (hrange > 0.f) ? (hmn + s1 * hrange) : s1;
        float c  = lz ? cv : s2;
        hout[h] = 0.5f * hv + 0.5f * c;
        cout[h] = ce[h];
    }
}

// ---------------- generic tiled GEMM: C[m][n] = A(m,:)·W(n,:) + bias (+bias2) ----------------
// BM=BN=64, BK=16, 256 threads, 4x4 micro-tiles, reg-prefetch double-buffering of gmem loads.
// AMODE 0: row m -> A + m*K (row-major).  AMODE 1: m = t*NB+b, row -> A + (b*NT+t)*K.
template<int AMODE, bool RELU, bool MASKZ, bool HB2>
__global__ void __launch_bounds__(256) gemm64_kernel(
    const float* __restrict__ A, const float* __restrict__ W,
    const float* __restrict__ bias, const float* __restrict__ bias2,
    float* __restrict__ Cout, int N, int K,
    const int* __restrict__ lens)
{
    const int m0 = blockIdx.y * 64;
    const int n0 = blockIdx.x * 64;
    __shared__ float As[16][68];
    __shared__ float Ws[16][68];
    const int tid = threadIdx.x;
    const int ty = tid >> 4, tx = tid & 15;
    const int lr = tid >> 2, lf = tid & 3;

    const float* arow;
    {
        int m = m0 + lr;
        if (AMODE == 1) { int t = m / NB; int b = m - t * NB; arow = A + ((size_t)b * NT + t) * K; }
        else            { arow = A + (size_t)m * K; }
    }
    const float* wrow = W + (size_t)(n0 + lr) * K;

    float4 pa = *(const float4*)(arow + lf * 4);
    float4 pw = *(const float4*)(wrow + lf * 4);

    float acc[4][4] = {};

    for (int k0 = 0; k0 < K; k0 += 16) {
        As[lf*4+0][lr] = pa.x; As[lf*4+1][lr] = pa.y; As[lf*4+2][lr] = pa.z; As[lf*4+3][lr] = pa.w;
        Ws[lf*4+0][lr] = pw.x; Ws[lf*4+1][lr] = pw.y; Ws[lf*4+2][lr] = pw.z; Ws[lf*4+3][lr] = pw.w;
        __syncthreads();
        int kn = k0 + 16;
        if (kn < K) {
            pa = *(const float4*)(arow + kn + lf * 4);
            pw = *(const float4*)(wrow + kn + lf * 4);
        }
#pragma unroll
        for (int k = 0; k < 16; k++) {
            float4 av = *(const float4*)&As[k][ty * 4];
            float4 wv = *(const float4*)&Ws[k][tx * 4];
            fma16(acc, av, wv);
        }
        __syncthreads();
    }

    float4 bv = *(const float4*)&bias[n0 + tx * 4];
    float4 b2v = make_float4(0.f, 0.f, 0.f, 0.f);
    if (HB2) b2v = *(const float4*)&bias2[n0 + tx * 4];

#pragma unroll
    for (int i = 0; i < 4; i++) {
        int m = m0 + ty * 4 + i;
        bool zrow = false;
        if (MASKZ) zrow = (lens[m / NT] == 0);
        float4 r;
        r.x = acc[i][0] + bv.x + b2v.x;
        r.y = acc[i][1] + bv.y + b2v.y;
        r.z = acc[i][2] + bv.z + b2v.z;
        r.w = acc[i][3] + bv.w + b2v.w;
        if (RELU) {
            r.x = fmaxf(r.x, 0.f); r.y = fmaxf(r.y, 0.f);
            r.z = fmaxf(r.z, 0.f); r.w = fmaxf(r.w, 0.f);
        }
        if (MASKZ && zrow) { r.x = 0.f; r.y = 0.f; r.z = 0.f; r.w = 0.f; }
        *(float4*)&Cout[(size_t)m * N + n0 + tx * 4] = r;
    }
}

// ---------------- LSTM step, layer 0: gates = pre0[t] + h0 @ Whh0^T; fused update ----------------
// 128 blocks; block owns 8 hidden units (all 4 gates) x all 64 batch rows.
__global__ void __launch_bounds__(128) lstm_step0_kernel(
    const float* __restrict__ whh, const int* __restrict__ lens, int t)
{
    const int u0 = blockIdx.x * 8;
    const int tid = threadIdx.x;
    const int ping = t & 1;
    const float* __restrict__ hprev = g_hbuf[0][ping];

    __shared__ float As[16][68];
    __shared__ float Ws[16][36];
    __shared__ float sg[32][65];

    const int ty = tid >> 3, tx = tid & 7;
    const int lr = tid >> 2, lf = tid & 3;
    const int wr = tid >> 2, wf = tid & 3;
    const int wgate = wr >> 3;
    const int wu = u0 + (wr & 7);
    const float* __restrict__ wptr = whh + ((size_t)(wgate * NH + wu)) * NH;
    const float* __restrict__ ap0 = hprev + (size_t)lr * NH;
    const float* __restrict__ ap1 = hprev + (size_t)(lr + 32) * NH;

    float4 pa0 = *(const float4*)(ap0 + lf * 4);
    float4 pa1 = *(const float4*)(ap1 + lf * 4);
    float4 pw  = *(const float4*)(wptr + wf * 4);

    float acc[4][4] = {};
    for (int k0 = 0; k0 < NH; k0 += 16) {
        As[lf*4+0][lr] = pa0.x; As[lf*4+1][lr] = pa0.y; As[lf*4+2][lr] = pa0.z; As[lf*4+3][lr] = pa0.w;
        As[lf*4+0][lr+32] = pa1.x; As[lf*4+1][lr+32] = pa1.y; As[lf*4+2][lr+32] = pa1.z; As[lf*4+3][lr+32] = pa1.w;
        Ws[wf*4+0][wr] = pw.x; Ws[wf*4+1][wr] = pw.y; Ws[wf*4+2][wr] = pw.z; Ws[wf*4+3][wr] = pw.w;
        __syncthreads();
        int kn = k0 + 16;
        if (kn < NH) {
            pa0 = *(const float4*)(ap0 + kn + lf * 4);
            pa1 = *(const float4*)(ap1 + kn + lf * 4);
            pw  = *(const float4*)(wptr + kn + wf * 4);
        }
#pragma unroll
        for (int k = 0; k < 16; k++) {
            float4 av = *(const float4*)&As[k][ty * 4];
            float4 wv = *(const float4*)&Ws[k][tx * 4];
            fma16(acc, av, wv);
        }
        __syncthreads();
    }

#pragma unroll
    for (int i = 0; i < 4; i++) {
        int m = ty * 4 + i;
        const float* prow = g_pre0 + ((size_t)(t * NB + m)) * G4;
#pragma unroll
        for (int j = 0; j < 4; j++) {
            int nl = tx * 4 + j;
            int jcol = (nl >> 3) * NH + u0 + (nl & 7);
            sg[nl][m] = acc[i][j] + prow[jcol];
        }
    }
    __syncthreads();

#pragma unroll
    for (int q = 0; q < 4; q++) {
        int item = tid + 128 * q;       // 0..511
        int u = item & 7;
        int b = item >> 3;              // 0..63
        float iv = sigmoidf_(sg[u][b]);
        float fv = sigmoidf_(sg[8 + u][b]);
        float gv = tanhf(sg[16 + u][b]);
        float ov = sigmoidf_(sg[24 + u][b]);
        size_t off = (size_t)b * NH + u0 + u;
        float c_old = g_c[0][off];
        int lnv = lens[b]; if (lnv < 1) lnv = 1;
        bool valid = (t < lnv);
        float c_new = fv * c_old + iv * gv;
        float h_new = ov * tanhf(c_new);
        g_c[0][off] = valid ? c_new : c_old;
        g_hbuf[0][ping ^ 1][off] = valid ? h_new : hprev[off];
        g_h0out[off] = valid ? h_new : 0.f;
    }
}

// ---------------- LSTM step, layer 1: gates = h0out@Wih1^T + h1@Whh1^T + biases; fused update ----------------
__global__ void __launch_bounds__(128) lstm_step1_kernel(
    const float* __restrict__ wih, const float* __restrict__ whh,
    const float* __restrict__ bih, const float* __restrict__ bhh,
    const int* __restrict__ lens, int t)
{
    const int u0 = blockIdx.x * 8;
    const int tid = threadIdx.x;
    const int ping = t & 1;
    const float* __restrict__ hprev = g_hbuf[1][ping];
    const float* __restrict__ h0o = g_h0out;

    __shared__ float As[16][68];
    __shared__ float Ws[16][36];
    __shared__ float sg[32][65];

    const int ty = tid >> 3, tx = tid & 7;
    const int lr = tid >> 2, lf = tid & 3;
    const int wr = tid >> 2, wf = tid & 3;
    const int wgate = wr >> 3;
    const int wu = u0 + (wr & 7);
    const size_t wrowoff = ((size_t)(wgate * NH + wu)) * NH;

    float4 pa0 = *(const float4*)(h0o + (size_t)lr * NH + lf * 4);
    float4 pa1 = *(const float4*)(h0o + (size_t)(lr + 32) * NH + lf * 4);
    float4 pw  = *(const float4*)(wih + wrowoff + wf * 4);

    float acc[4][4] = {};
    for (int k0 = 0; k0 < 2 * NH; k0 += 16) {
        As[lf*4+0][lr] = pa0.x; As[lf*4+1][lr] = pa0.y; As[lf*4+2][lr] = pa0.z; As[lf*4+3][lr] = pa0.w;
        As[lf*4+0][lr+32] = pa1.x; As[lf*4+1][lr+32] = pa1.y; As[lf*4+2][lr+32] = pa1.z; As[lf*4+3][lr+32] = pa1.w;
        Ws[wf*4+0][wr] = pw.x; Ws[wf*4+1][wr] = pw.y; Ws[wf*4+2][wr] = pw.z; Ws[wf*4+3][wr] = pw.w;
        __syncthreads();
        int kn = k0 + 16;
        if (kn < 2 * NH) {
            const float* ab = (kn < NH) ? h0o : hprev;
            const float* wb = (kn < NH) ? wih : whh;
            int ko = kn & (NH - 1);
            pa0 = *(const float4*)(ab + (size_t)lr * NH + ko + lf * 4);
            pa1 = *(const float4*)(ab + (size_t)(lr + 32) * NH + ko + lf * 4);
            pw  = *(const float4*)(wb + wrowoff + ko + wf * 4);
        }
#pragma unroll
        for (int k = 0; k < 16; k++) {
            float4 av = *(const float4*)&As[k][ty * 4];
            float4 wv = *(const float4*)&Ws[k][tx * 4];
            fma16(acc, av, wv);
        }
        __syncthreads();
    }

#pragma unroll
    for (int i = 0; i < 4; i++) {
        int m = ty * 4 + i;
#pragma unroll
        for (int j = 0; j < 4; j++) {
            int nl = tx * 4 + j;
            int jcol = (nl >> 3) * NH + u0 + (nl & 7);
            sg[nl][m] = acc[i][j] + bih[jcol] + bhh[jcol];
        }
    }
    __syncthreads();

#pragma unroll
    for (int q = 0; q < 4; q++) {
        int item = tid + 128 * q;
        int u = item & 7;
        int b = item >> 3;
        float iv = sigmoidf_(sg[u][b]);
        float fv = sigmoidf_(sg[8 + u][b]);
        float gv = tanhf(sg[16 + u][b]);
        float ov = sigmoidf_(sg[24 + u][b]);
        size_t off = (size_t)b * NH + u0 + u;
        float c_old = g_c[1][off];
        int lnv = lens[b]; if (lnv < 1) lnv = 1;
        bool valid = (t < lnv);
        float c_new = fv * c_old + iv * gv;
        float h_new = ov * tanhf(c_new);
        g_c[1][off] = valid ? c_new : c_old;
        g_hbuf[1][ping ^ 1][off] = valid ? h_new : hprev[off];
        g_lstm_out[((size_t)b * NT + t) * NH + u0 + u] = valid ? h_new : 0.f;
    }
}

// ---------------- finalize hn / cn with zero-length masking ----------------
__global__ void finalize_hc_kernel(float* __restrict__ hn, float* __restrict__ cn,
                                   const int* __restrict__ lens)
{
    int idx = blockIdx.x * 256 + threadIdx.x;   // < NL*NB*NH
    int l = idx >> 16;                          // / (NB*NH)
    int r = idx & 65535;
    int b = r >> 10;                            // / NH
    bool z = (lens[b] == 0);
    hn[idx] = z ? 0.f : g_hbuf[l][0][r];        // T even -> final state is in buffer 0
    cn[idx] = z ? 0.f : g_c[l][r];
}

// ---------------- entry point ----------------
extern "C" void kernel_launch(void* const* d_in, const int* in_sizes, int n_in,
                              void* d_out, int out_size)
{
    (void)in_sizes; (void)n_in; (void)out_size;
    const float* step_input = (const float*)d_in[0];
    const float* clstm      = (const float*)d_in[1];
    const float* hidden     = (const float*)d_in[2];
    const float* cell       = (const float*)d_in[3];
    const int* lens         = (const int*)d_in[4];
    const float* w_ih0 = (const float*)d_in[5];
    const float* w_hh0 = (const float*)d_in[6];
    const float* b_ih0 = (const float*)d_in[7];
    const float* b_hh0 = (const float*)d_in[8];
    const float* w_ih1 = (const float*)d_in[9];
    const float* w_hh1 = (const float*)d_in[10];
    const float* b_ih1 = (const float*)d_in[11];
    const float* b_hh1 = (const float*)d_in[12];
    const float* w1 = (const float*)d_in[13];
    const float* b1 = (const float*)d_in[14];
    const float* w2 = (const float*)d_in[15];
    const float* b2 = (const float*)d_in[16];

    float* out = (float*)d_out;
    float* out_logits = out;
    float* out_hn = out + (size_t)NB * NT * NO;
    float* out_cn = out_hn + (size_t)NL * NB * NH;

    float *pre0p, *loutp, *fc1p;
    cudaGetSymbolAddress((void**)&pre0p, g_pre0);
    cudaGetSymbolAddress((void**)&loutp, g_lstm_out);
    cudaGetSymbolAddress((void**)&fc1p, g_fc1);

    // 1) weighted-hidden init + cell copy
    init_state_kernel<<<NL * NB, 256>>>(clstm, hidden, cell, lens);

    // 2) pre0[t][b][:] = x[b][t] @ Wih0^T + b_ih0 + b_hh0   (M=T*B, N=4H, K=I)
    gemm64_kernel<1, false, false, true><<<dim3(G4 / 64, (NB * NT) / 64), 256>>>(
        step_input, w_ih0, b_ih0, b_hh0, pre0p, G4, NI, nullptr);

    // 3) sequential LSTM
    for (int t = 0; t < NT; t++) {
        lstm_step0_kernel<<<128, 128>>>(w_hh0, lens, t);
        lstm_step1_kernel<<<128, 128>>>(w_ih1, w_hh1, b_ih1, b_hh1, lens, t);
    }

    // 4) FC1: relu(lstm_out @ w1^T + b1)
    gemm64_kernel<0, true, false, false><<<dim3(NH / 64, (NB * NT) / 64), 256>>>(
        loutp, w1, b1, nullptr, fc1p, NH, NH, nullptr);

    // 5) FC2: relu(fc1 @ w2^T + b2), zeroed for zero-length batches
    gemm64_kernel<0, true, true, false><<<dim3(NO / 64, (NB * NT) / 64), 256>>>(
        fc1p, w2, b2, nullptr, out_logits, NO, NH, lens);

    // 6) hn / cn
    finalize_hc_kernel<<<(NL * NB * NH) / 256, 256>>>(out_hn, out_cn, lens);
}

// round 3
// speedup vs baseline: 1.0066x; 1.0066x over previous
#include <cuda_runtime.h>
#include <math.h>

#define NL 2
#define NB 64
#define NT 256
#define NI 512
#define NH 1024
#define NO 256
#define G4 (4*NH)   // 4096

// ---------------- scratch (device globals; no allocation allowed) ----------------
__device__ __align__(16) float g_pre0[NT*NB*G4];        // [t][b][4H]  (~268 MB)
__device__ __align__(16) float g_hbuf[NL][2][NB*NH];    // ping-pong h state per layer
__device__ __align__(16) float g_c[NL][NB*NH];          // c state (block-owned, in place)
__device__ __align__(16) float g_h0out[NB*NH];          // masked layer0 output (layer1 input)
__device__ __align__(16) float g_lstm_out[NB*NT*NH];    // [b][t][H]
__device__ __align__(16) float g_fc1[NB*NT*NH];

// ---------------- helpers ----------------
__device__ __forceinline__ void fma16(float (&acc)[4][4], float4 av, float4 wv) {
    acc[0][0] = fmaf(av.x, wv.x, acc[0][0]);
    acc[0][1] = fmaf(av.x, wv.y, acc[0][1]);
    acc[0][2] = fmaf(av.x, wv.z, acc[0][2]);
    acc[0][3] = fmaf(av.x, wv.w, acc[0][3]);
    acc[1][0] = fmaf(av.y, wv.x, acc[1][0]);
    acc[1][1] = fmaf(av.y, wv.y, acc[1][1]);
    acc[1][2] = fmaf(av.y, wv.z, acc[1][2]);
    acc[1][3] = fmaf(av.y, wv.w, acc[1][3]);
    acc[2][0] = fmaf(av.z, wv.x, acc[2][0]);
    acc[2][1] = fmaf(av.z, wv.y, acc[2][1]);
    acc[2][2] = fmaf(av.z, wv.z, acc[2][2]);
    acc[2][3] = fmaf(av.z, wv.w, acc[2][3]);
    acc[3][0] = fmaf(av.w, wv.x, acc[3][0]);
    acc[3][1] = fmaf(av.w, wv.y, acc[3][1]);
    acc[3][2] = fmaf(av.w, wv.z, acc[3][2]);
    acc[3][3] = fmaf(av.w, wv.w, acc[3][3]);
}

__device__ __forceinline__ float sigmoidf_(float x) { return 1.f / (1.f + expf(-x)); }

// ---------------- init: weighted hidden + cell copy ----------------
__global__ void init_state_kernel(const float* __restrict__ clstm,
                                  const float* __restrict__ hidden,
                                  const float* __restrict__ cell,
                                  const int* __restrict__ lens)
{
    int l = blockIdx.x >> 6;       // / NB
    int b = blockIdx.x & 63;
    const float* cl = clstm + (size_t)b * NH;
    const float* hd = hidden + ((size_t)l * NB + b) * NH;
    const float* ce = cell   + ((size_t)l * NB + b) * NH;

    float cmn = 3.4e38f, cmx = -3.4e38f, hmn = 3.4e38f, hmx = -3.4e38f;
    for (int h = threadIdx.x; h < NH; h += 256) {
        float cv = cl[h], hv = hd[h];
        cmn = fminf(cmn, cv); cmx = fmaxf(cmx, cv);
        hmn = fminf(hmn, hv); hmx = fmaxf(hmx, hv);
    }
#pragma unroll
    for (int o = 16; o; o >>= 1) {
        cmn = fminf(cmn, __shfl_xor_sync(0xffffffffu, cmn, o));
        cmx = fmaxf(cmx, __shfl_xor_sync(0xffffffffu, cmx, o));
        hmn = fminf(hmn, __shfl_xor_sync(0xffffffffu, hmn, o));
        hmx = fmaxf(hmx, __shfl_xor_sync(0xffffffffu, hmx, o));
    }
    __shared__ float s[4][8];
    __shared__ float fs[4];
    int w = threadIdx.x >> 5, ln = threadIdx.x & 31;
    if (ln == 0) { s[0][w] = cmn; s[1][w] = cmx; s[2][w] = hmn; s[3][w] = hmx; }
    __syncthreads();
    if (threadIdx.x < 4) {
        float v = s[threadIdx.x][0];
        bool ismin = (threadIdx.x == 0) || (threadIdx.x == 2);
#pragma unroll
        for (int i = 1; i < 8; i++) {
            float x = s[threadIdx.x][i];
            v = ismin ? fminf(v, x) : fmaxf(v, x);
        }
        fs[threadIdx.x] = v;
    }
    __syncthreads();
    cmn = fs[0]; cmx = fs[1]; hmn = fs[2]; hmx = fs[3];
    float crange = cmx - cmn, hrange = hmx - hmn;
    bool lz = (lens[b] == 0);

    float* hout = g_hbuf[l][0] + (size_t)b * NH;
    float* cout = g_c[l]       + (size_t)b * NH;
    for (int h = threadIdx.x; h < NH; h += 256) {
        float cv = cl[h], hv = hd[h];
        float s1 = (crange > 0.f) ? (cv - cmn) / crange : cv;
        float s2 = (hrange > 0.f) ? (hmn + s1 * hrange) : s1;
        float c  = lz ? cv : s2;
        hout[h] = 0.5f * hv + 0.5f * c;
        cout[h] = ce[h];
    }
}

// ---------------- generic tiled GEMM: C[m][n] = A(m,:)·W(n,:) + bias (+bias2) ----------------
// BM=BN=64, BK=16, 256 threads, 4x4 micro-tiles, reg-prefetch double-buffering of gmem loads.
// AMODE 0: row m -> A + m*K (row-major).  AMODE 1: m = t*NB+b, row -> A + (b*NT+t)*K.
template<int AMODE, bool RELU, bool MASKZ, bool HB2>
__global__ void __launch_bounds__(256) gemm64_kernel(
    const float* __restrict__ A, const float* __restrict__ W,
    const float* __restrict__ bias, const float* __restrict__ bias2,
    float* __restrict__ Cout, int N, int K,
    const int* __restrict__ lens)
{
    const int m0 = blockIdx.y * 64;
    const int n0 = blockIdx.x * 64;
    __shared__ float As[16][68];
    __shared__ float Ws[16][68];
    const int tid = threadIdx.x;
    const int ty = tid >> 4, tx = tid & 15;
    const int lr = tid >> 2, lf = tid & 3;

    const float* arow;
    {
        int m = m0 + lr;
        if (AMODE == 1) { int t = m / NB; int b = m - t * NB; arow = A + ((size_t)b * NT + t) * K; }
        else            { arow = A + (size_t)m * K; }
    }
    const float* wrow = W + (size_t)(n0 + lr) * K;

    float4 pa = *(const float4*)(arow + lf * 4);
    float4 pw = *(const float4*)(wrow + lf * 4);

    float acc[4][4] = {};

    for (int k0 = 0; k0 < K; k0 += 16) {
        As[lf*4+0][lr] = pa.x; As[lf*4+1][lr] = pa.y; As[lf*4+2][lr] = pa.z; As[lf*4+3][lr] = pa.w;
        Ws[lf*4+0][lr] = pw.x; Ws[lf*4+1][lr] = pw.y; Ws[lf*4+2][lr] = pw.z; Ws[lf*4+3][lr] = pw.w;
        __syncthreads();
        int kn = k0 + 16;
        if (kn < K) {
            pa = *(const float4*)(arow + kn + lf * 4);
            pw = *(const float4*)(wrow + kn + lf * 4);
        }
#pragma unroll
        for (int k = 0; k < 16; k++) {
            float4 av = *(const float4*)&As[k][ty * 4];
            float4 wv = *(const float4*)&Ws[k][tx * 4];
            fma16(acc, av, wv);
        }
        __syncthreads();
    }

    float4 bv = *(const float4*)&bias[n0 + tx * 4];
    float4 b2v = make_float4(0.f, 0.f, 0.f, 0.f);
    if (HB2) b2v = *(const float4*)&bias2[n0 + tx * 4];

#pragma unroll
    for (int i = 0; i < 4; i++) {
        int m = m0 + ty * 4 + i;
        bool zrow = false;
        if (MASKZ) zrow = (lens[m / NT] == 0);
        float4 r;
        r.x = acc[i][0] + bv.x + b2v.x;
        r.y = acc[i][1] + bv.y + b2v.y;
        r.z = acc[i][2] + bv.z + b2v.z;
        r.w = acc[i][3] + bv.w + b2v.w;
        if (RELU) {
            r.x = fmaxf(r.x, 0.f); r.y = fmaxf(r.y, 0.f);
            r.z = fmaxf(r.z, 0.f); r.w = fmaxf(r.w, 0.f);
        }
        if (MASKZ && zrow) { r.x = 0.f; r.y = 0.f; r.z = 0.f; r.w = 0.f; }
        *(float4*)&Cout[(size_t)m * N + n0 + tx * 4] = r;
    }
}

// ---------------- LSTM step, layer 0: gates = pre0[t] + h0 @ Whh0^T; fused update ----------------
// 128 blocks; block owns 8 hidden units (all 4 gates) x all 64 batch rows.
__global__ void __launch_bounds__(128) lstm_step0_kernel(
    const float* __restrict__ whh, const int* __restrict__ lens, int t)
{
    const int u0 = blockIdx.x * 8;
    const int tid = threadIdx.x;
    const int ping = t & 1;
    const float* __restrict__ hprev = g_hbuf[0][ping];

    __shared__ float As[16][68];
    __shared__ float Ws[16][36];
    __shared__ float sg[32][65];

    const int ty = tid >> 3, tx = tid & 7;
    const int lr = tid >> 2, lf = tid & 3;
    const int wr = tid >> 2, wf = tid & 3;
    const int wgate = wr >> 3;
    const int wu = u0 + (wr & 7);
    const float* __restrict__ wptr = whh + ((size_t)(wgate * NH + wu)) * NH;
    const float* __restrict__ ap0 = hprev + (size_t)lr * NH;
    const float* __restrict__ ap1 = hprev + (size_t)(lr + 32) * NH;

    float4 pa0 = *(const float4*)(ap0 + lf * 4);
    float4 pa1 = *(const float4*)(ap1 + lf * 4);
    float4 pw  = *(const float4*)(wptr + wf * 4);

    float acc[4][4] = {};
    for (int k0 = 0; k0 < NH; k0 += 16) {
        As[lf*4+0][lr] = pa0.x; As[lf*4+1][lr] = pa0.y; As[lf*4+2][lr] = pa0.z; As[lf*4+3][lr] = pa0.w;
        As[lf*4+0][lr+32] = pa1.x; As[lf*4+1][lr+32] = pa1.y; As[lf*4+2][lr+32] = pa1.z; As[lf*4+3][lr+32] = pa1.w;
        Ws[wf*4+0][wr] = pw.x; Ws[wf*4+1][wr] = pw.y; Ws[wf*4+2][wr] = pw.z; Ws[wf*4+3][wr] = pw.w;
        __syncthreads();
        int kn = k0 + 16;
        if (kn < NH) {
            pa0 = *(const float4*)(ap0 + kn + lf * 4);
            pa1 = *(const float4*)(ap1 + kn + lf * 4);
            pw  = *(const float4*)(wptr + kn + wf * 4);
        }
#pragma unroll
        for (int k = 0; k < 16; k++) {
            float4 av = *(const float4*)&As[k][ty * 4];
            float4 wv = *(const float4*)&Ws[k][tx * 4];
            fma16(acc, av, wv);
        }
        __syncthreads();
    }

#pragma unroll
    for (int i = 0; i < 4; i++) {
        int m = ty * 4 + i;
        const float* prow = g_pre0 + ((size_t)(t * NB + m)) * G4;
#pragma unroll
        for (int j = 0; j < 4; j++) {
            int nl = tx * 4 + j;
            int jcol = (nl >> 3) * NH + u0 + (nl & 7);
            sg[nl][m] = acc[i][j] + prow[jcol];
        }
    }
    __syncthreads();

#pragma unroll
    for (int q = 0; q < 4; q++) {
        int item = tid + 128 * q;       // 0..511
        int u = item & 7;
        int b = item >> 3;              // 0..63
        float iv = sigmoidf_(sg[u][b]);
        float fv = sigmoidf_(sg[8 + u][b]);
        float gv = tanhf(sg[16 + u][b]);
        float ov = sigmoidf_(sg[24 + u][b]);
        size_t off = (size_t)b * NH + u0 + u;
        float c_old = g_c[0][off];
        int lnv = lens[b]; if (lnv < 1) lnv = 1;
        bool valid = (t < lnv);
        float c_new = fv * c_old + iv * gv;
        float h_new = ov * tanhf(c_new);
        g_c[0][off] = valid ? c_new : c_old;
        g_hbuf[0][ping ^ 1][off] = valid ? h_new : hprev[off];
        g_h0out[off] = valid ? h_new : 0.f;
    }
}

// ---------------- LSTM step, layer 1: gates = h0out@Wih1^T + h1@Whh1^T + biases; fused update ----------------
__global__ void __launch_bounds__(128) lstm_step1_kernel(
    const float* __restrict__ wih, const float* __restrict__ whh,
    const float* __restrict__ bih, const float* __restrict__ bhh,
    const int* __restrict__ lens, int t)
{
    const int u0 = blockIdx.x * 8;
    const int tid = threadIdx.x;
    const int ping = t & 1;
    const float* __restrict__ hprev = g_hbuf[1][ping];
    const float* __restrict__ h0o = g_h0out;

    __shared__ float As[16][68];
    __shared__ float Ws[16][36];
    __shared__ float sg[32][65];

    const int ty = tid >> 3, tx = tid & 7;
    const int lr = tid >> 2, lf = tid & 3;
    const int wr = tid >> 2, wf = tid & 3;
    const int wgate = wr >> 3;
    const int wu = u0 + (wr & 7);
    const size_t wrowoff = ((size_t)(wgate * NH + wu)) * NH;

    float4 pa0 = *(const float4*)(h0o + (size_t)lr * NH + lf * 4);
    float4 pa1 = *(const float4*)(h0o + (size_t)(lr + 32) * NH + lf * 4);
    float4 pw  = *(const float4*)(wih + wrowoff + wf * 4);

    float acc[4][4] = {};
    for (int k0 = 0; k0 < 2 * NH; k0 += 16) {
        As[lf*4+0][lr] = pa0.x; As[lf*4+1][lr] = pa0.y; As[lf*4+2][lr] = pa0.z; As[lf*4+3][lr] = pa0.w;
        As[lf*4+0][lr+32] = pa1.x; As[lf*4+1][lr+32] = pa1.y; As[lf*4+2][lr+32] = pa1.z; As[lf*4+3][lr+32] = pa1.w;
        Ws[wf*4+0][wr] = pw.x; Ws[wf*4+1][wr] = pw.y; Ws[wf*4+2][wr] = pw.z; Ws[wf*4+3][wr] = pw.w;
        __syncthreads();
        int kn = k0 + 16;
        if (kn < 2 * NH) {
            const float* ab = (kn < NH) ? h0o : hprev;
            const float* wb = (kn < NH) ? wih : whh;
            int ko = kn & (NH - 1);
            pa0 = *(const float4*)(ab + (size_t)lr * NH + ko + lf * 4);
            pa1 = *(const float4*)(ab + (size_t)(lr + 32) * NH + ko + lf * 4);
            pw  = *(const float4*)(wb + wrowoff + ko + wf * 4);
        }
#pragma unroll
        for (int k = 0; k < 16; k++) {
            float4 av = *(const float4*)&As[k][ty * 4];
            float4 wv = *(const float4*)&Ws[k][tx * 4];
            fma16(acc, av, wv);
        }
        __syncthreads();
    }

#pragma unroll
    for (int i = 0; i < 4; i++) {
        int m = ty * 4 + i;
#pragma unroll
        for (int j = 0; j < 4; j++) {
            int nl = tx * 4 + j;
            int jcol = (nl >> 3) * NH + u0 + (nl & 7);
            sg[nl][m] = acc[i][j] + bih[jcol] + bhh[jcol];
        }
    }
    __syncthreads();

#pragma unroll
    for (int q = 0; q < 4; q++) {
        int item = tid + 128 * q;
        int u = item & 7;
        int b = item >> 3;
        float iv = sigmoidf_(sg[u][b]);
        float fv = sigmoidf_(sg[8 + u][b]);
        float gv = tanhf(sg[16 + u][b]);
        float ov = sigmoidf_(sg[24 + u][b]);
        size_t off = (size_t)b * NH + u0 + u;
        float c_old = g_c[1][off];
        int lnv = lens[b]; if (lnv < 1) lnv = 1;
        bool valid = (t < lnv);
        float c_new = fv * c_old + iv * gv;
        float h_new = ov * tanhf(c_new);
        g_c[1][off] = valid ? c_new : c_old;
        g_hbuf[1][ping ^ 1][off] = valid ? h_new : hprev[off];
        g_lstm_out[((size_t)b * NT + t) * NH + u0 + u] = valid ? h_new : 0.f;
    }
}

// ---------------- finalize hn / cn with zero-length masking ----------------
__global__ void finalize_hc_kernel(float* __restrict__ hn, float* __restrict__ cn,
                                   const int* __restrict__ lens)
{
    int idx = blockIdx.x * 256 + threadIdx.x;   // < NL*NB*NH
    int l = idx >> 16;                          // / (NB*NH)
    int r = idx & 65535;
    int b = r >> 10;                            // / NH
    bool z = (lens[b] == 0);
    hn[idx] = z ? 0.f : g_hbuf[l][0][r];        // T even -> final state is in buffer 0
    cn[idx] = z ? 0.f : g_c[l][r];
}

// ---------------- entry point ----------------
extern "C" void kernel_launch(void* const* d_in, const int* in_sizes, int n_in,
                              void* d_out, int out_size)
{
    (void)in_sizes; (void)n_in; (void)out_size;
    const float* step_input = (const float*)d_in[0];
    const float* clstm      = (const float*)d_in[1];
    const float* hidden     = (const float*)d_in[2];
    const float* cell       = (const float*)d_in[3];
    const int* lens         = (const int*)d_in[4];
    const float* w_ih0 = (const float*)d_in[5];
    const float* w_hh0 = (const float*)d_in[6];
    const float* b_ih0 = (const float*)d_in[7];
    const float* b_hh0 = (const float*)d_in[8];
    const float* w_ih1 = (const float*)d_in[9];
    const float* w_hh1 = (const float*)d_in[10];
    const float* b_ih1 = (const float*)d_in[11];
    const float* b_hh1 = (const float*)d_in[12];
    const float* w1 = (const float*)d_in[13];
    const float* b1 = (const float*)d_in[14];
    const float* w2 = (const float*)d_in[15];
    const float* b2 = (const float*)d_in[16];

    float* out = (float*)d_out;
    float* out_logits = out;
    float* out_hn = out + (size_t)NB * NT * NO;
    float* out_cn = out_hn + (size_t)NL * NB * NH;

    float *pre0p, *loutp, *fc1p;
    cudaGetSymbolAddress((void**)&pre0p, g_pre0);
    cudaGetSymbolAddress((void**)&loutp, g_lstm_out);
    cudaGetSymbolAddress((void**)&fc1p, g_fc1);

    // 1) weighted-hidden init + cell copy
    init_state_kernel<<<NL * NB, 256>>>(clstm, hidden, cell, lens);

    // 2) pre0[t][b][:] = x[b][t] @ Wih0^T + b_ih0 + b_hh0   (M=T*B, N=4H, K=I)
    gemm64_kernel<1, false, false, true><<<dim3(G4 / 64, (NB * NT) / 64), 256>>>(
        step_input, w_ih0, b_ih0, b_hh0, pre0p, G4, NI, nullptr);

    // 3) sequential LSTM
    for (int t = 0; t < NT; t++) {
        lstm_step0_kernel<<<128, 128>>>(w_hh0, lens, t);
        lstm_step1_kernel<<<128, 128>>>(w_ih1, w_hh1, b_ih1, b_hh1, lens, t);
    }

    // 4) FC1: relu(lstm_out @ w1^T + b1)
    gemm64_kernel<0, true, false, false><<<dim3(NH / 64, (NB * NT) / 64), 256>>>(
        loutp, w1, b1, nullptr, fc1p, NH, NH, nullptr);

    // 5) FC2: relu(fc1 @ w2^T + b2), zeroed for zero-length batches
    gemm64_kernel<0, true, true, false><<<dim3(NO / 64, (NB * NT) / 64), 256>>>(
        fc1p, w2, b2, nullptr, out_logits, NO, NH, lens);

    // 6) hn / cn
    finalize_hc_kernel<<<(NL * NB * NH) / 256, 256>>>(out_hn, out_cn, lens);
}

// round 5
// speedup vs baseline: 1.2492x; 1.2410x over previous
#include <cuda_runtime.h>
#include <cuda_bf16.h>
#include <math.h>
#include <stdint.h>

#define NL 2
#define NB 64
#define NT 256
#define NI 512
#define NH 1024
#define NO 256
#define G4 4096

// ---------------- scratch (device globals) ----------------
__device__ __align__(16) float g_pre0[NT*NB*G4];        // [t][b][4H]
__device__ __align__(16) float g_lstm_out[NB*NT*NH];    // [b][t][H]
__device__ __align__(16) float g_fc1[NB*NT*NH];
__device__ __align__(16) float g_c0[NB*NH], g_c1[NB*NH];
__device__ __align__(16) float g_h0f[NB*NH], g_h1f[NB*NH];
__device__ __align__(16) __nv_bfloat16 g_h0bf[2][2][NB*NH];   // [ping][hi/lo]
__device__ __align__(16) __nv_bfloat16 g_h1bf[2][2][NB*NH];
__device__ __align__(16) __nv_bfloat16 g_h0in[2][NB*NH];      // [hi/lo] layer1 input
__device__ __align__(16) __nv_bfloat16 g_w0p[2][(size_t)G4*NH];     // reordered Whh0 hi/lo
__device__ __align__(16) __nv_bfloat16 g_w1p[2][(size_t)G4*2*NH];   // reordered [Wih1|Whh1] hi/lo

// ---------------- low-level helpers ----------------
__device__ __forceinline__ uint32_t smem_u32(const void* p) {
    uint32_t a;
    asm("{ .reg .u64 t; cvta.to.shared.u64 t, %1; cvt.u32.u64 %0, t; }" : "=r"(a) : "l"(p));
    return a;
}
__device__ __forceinline__ void cpa16(uint32_t dst, const void* src) {
    asm volatile("cp.async.cg.shared.global [%0], [%1], 16;" :: "r"(dst), "l"(src) : "memory");
}
__device__ __forceinline__ void ldmx4(uint32_t* r, uint32_t addr) {
    asm volatile("ldmatrix.sync.aligned.m8n8.x4.shared.b16 {%0,%1,%2,%3}, [%4];"
                 : "=r"(r[0]), "=r"(r[1]), "=r"(r[2]), "=r"(r[3]) : "r"(addr));
}
__device__ __forceinline__ void mma16816(float (&d)[4], const uint32_t* a, const uint32_t* b) {
    asm volatile("mma.sync.aligned.m16n8k16.row.col.f32.bf16.bf16.f32 "
        "{%0,%1,%2,%3}, {%4,%5,%6,%7}, {%8,%9}, {%0,%1,%2,%3};"
        : "+f"(d[0]), "+f"(d[1]), "+f"(d[2]), "+f"(d[3])
        : "r"(a[0]), "r"(a[1]), "r"(a[2]), "r"(a[3]), "r"(b[0]), "r"(b[1]));
}
__device__ __forceinline__ float sigf(float x)  { return 1.f / (1.f + __expf(-x)); }
__device__ __forceinline__ float tanhft(float x){ return 2.f / (1.f + __expf(-2.f * x)) - 1.f; }

// ---------------- init: weighted hidden + cell copy + bf16 state ----------------
__global__ void init_state_kernel(const float* __restrict__ clstm,
                                  const float* __restrict__ hidden,
                                  const float* __restrict__ cell,
                                  const int* __restrict__ lens)
{
    int l = blockIdx.x >> 6;
    int b = blockIdx.x & 63;
    const float* cl = clstm + (size_t)b * NH;
    const float* hd = hidden + ((size_t)l * NB + b) * NH;
    const float* ce = cell   + ((size_t)l * NB + b) * NH;

    float cmn = 3.4e38f, cmx = -3.4e38f, hmn = 3.4e38f, hmx = -3.4e38f;
    for (int h = threadIdx.x; h < NH; h += 256) {
        float cv = cl[h], hv = hd[h];
        cmn = fminf(cmn, cv); cmx = fmaxf(cmx, cv);
        hmn = fminf(hmn, hv); hmx = fmaxf(hmx, hv);
    }
#pragma unroll
    for (int o = 16; o; o >>= 1) {
        cmn = fminf(cmn, __shfl_xor_sync(0xffffffffu, cmn, o));
        cmx = fmaxf(cmx, __shfl_xor_sync(0xffffffffu, cmx, o));
        hmn = fminf(hmn, __shfl_xor_sync(0xffffffffu, hmn, o));
        hmx = fmaxf(hmx, __shfl_xor_sync(0xffffffffu, hmx, o));
    }
    __shared__ float s[4][8];
    __shared__ float fs[4];
    int w = threadIdx.x >> 5, ln = threadIdx.x & 31;
    if (ln == 0) { s[0][w] = cmn; s[1][w] = cmx; s[2][w] = hmn; s[3][w] = hmx; }
    __syncthreads();
    if (threadIdx.x < 4) {
        float v = s[threadIdx.x][0];
        bool ismin = (threadIdx.x == 0) || (threadIdx.x == 2);
#pragma unroll
        for (int i = 1; i < 8; i++) {
            float x = s[threadIdx.x][i];
            v = ismin ? fminf(v, x) : fmaxf(v, x);
        }
        fs[threadIdx.x] = v;
    }
    __syncthreads();
    cmn = fs[0]; cmx = fs[1]; hmn = fs[2]; hmx = fs[3];
    float crange = cmx - cmn, hrange = hmx - hmn;
    bool lz = (lens[b] == 0);

    float* hf = l ? g_h1f : g_h0f;
    float* cf = l ? g_c1  : g_c0;
    __nv_bfloat16* bhi = l ? g_h1bf[0][0] : g_h0bf[0][0];
    __nv_bfloat16* blo = l ? g_h1bf[0][1] : g_h0bf[0][1];

    for (int h = threadIdx.x; h < NH; h += 256) {
        float cv = cl[h], hv = hd[h];
        float s1 = (crange > 0.f) ? (cv - cmn) / crange : cv;
        float s2 = (hrange > 0.f) ? (hmn + s1 * hrange) : s1;
        float c  = lz ? cv : s2;
        float hw = 0.5f * hv + 0.5f * c;
        size_t off = (size_t)b * NH + h;
        hf[off] = hw;
        cf[off] = ce[h];
        __nv_bfloat16 hi = __float2bfloat16(hw);
        bhi[off] = hi;
        blo[off] = __float2bfloat16(hw - __bfloat162float(hi));
    }
}

// ---------------- weight prep: unit-major reorder + bf16 hi/lo split ----------------
// dest row (within blk's 64) r: uu = r>>2, g = r&3  →  source row = g*NH + blk*16 + uu
__global__ void prep_w0_kernel(const float* __restrict__ w)
{
    int idx = blockIdx.x * 256 + threadIdx.x;
    int k = (idx & 255) * 4;
    int row = idx >> 8;
    int blk = row >> 6, r = row & 63;
    int uu = r >> 2, g = r & 3;
    int srow = g * NH + blk * 16 + uu;
    float4 v = *(const float4*)(w + (size_t)srow * NH + k);
    size_t o = (size_t)row * NH + k;
    float vv[4] = {v.x, v.y, v.z, v.w};
#pragma unroll
    for (int i = 0; i < 4; i++) {
        __nv_bfloat16 hi = __float2bfloat16(vv[i]);
        g_w0p[0][o + i] = hi;
        g_w0p[1][o + i] = __float2bfloat16(vv[i] - __bfloat162float(hi));
    }
}

__global__ void prep_w1_kernel(const float* __restrict__ wih, const float* __restrict__ whh)
{
    int idx = blockIdx.x * 256 + threadIdx.x;
    int k = (idx & 511) * 4;
    int row = idx >> 9;
    int blk = row >> 6, r = row & 63;
    int uu = r >> 2, g = r & 3;
    int srow = g * NH + blk * 16 + uu;
    const float* src = (k < NH) ? (wih + (size_t)srow * NH + k)
                                : (whh + (size_t)srow * NH + (k - NH));
    float4 v = *(const float4*)src;
    size_t o = (size_t)row * (2 * NH) + k;
    float vv[4] = {v.x, v.y, v.z, v.w};
#pragma unroll
    for (int i = 0; i < 4; i++) {
        __nv_bfloat16 hi = __float2bfloat16(vv[i]);
        g_w1p[0][o + i] = hi;
        g_w1p[1][o + i] = __float2bfloat16(vv[i] - __bfloat162float(hi));
    }
}

// ---------------- SIMT GEMM for pre0 / FC ----------------
__device__ __forceinline__ void fma16(float (&acc)[4][4], float4 av, float4 wv) {
    acc[0][0] = fmaf(av.x, wv.x, acc[0][0]); acc[0][1] = fmaf(av.x, wv.y, acc[0][1]);
    acc[0][2] = fmaf(av.x, wv.z, acc[0][2]); acc[0][3] = fmaf(av.x, wv.w, acc[0][3]);
    acc[1][0] = fmaf(av.y, wv.x, acc[1][0]); acc[1][1] = fmaf(av.y, wv.y, acc[1][1]);
    acc[1][2] = fmaf(av.y, wv.z, acc[1][2]); acc[1][3] = fmaf(av.y, wv.w, acc[1][3]);
    acc[2][0] = fmaf(av.z, wv.x, acc[2][0]); acc[2][1] = fmaf(av.z, wv.y, acc[2][1]);
    acc[2][2] = fmaf(av.z, wv.z, acc[2][2]); acc[2][3] = fmaf(av.z, wv.w, acc[2][3]);
    acc[3][0] = fmaf(av.w, wv.x, acc[3][0]); acc[3][1] = fmaf(av.w, wv.y, acc[3][1]);
    acc[3][2] = fmaf(av.w, wv.z, acc[3][2]); acc[3][3] = fmaf(av.w, wv.w, acc[3][3]);
}

template<int AMODE, bool RELU, bool MASKZ, bool HB2>
__global__ void __launch_bounds__(256) gemm64_kernel(
    const float* __restrict__ A, const float* __restrict__ W,
    const float* __restrict__ bias, const float* __restrict__ bias2,
    float* __restrict__ Cout, int N, int K,
    const int* __restrict__ lens)
{
    const int m0 = blockIdx.y * 64;
    const int n0 = blockIdx.x * 64;
    __shared__ float As[16][68];
    __shared__ float Ws[16][68];
    const int tid = threadIdx.x;
    const int ty = tid >> 4, tx = tid & 15;
    const int lr = tid >> 2, lf = tid & 3;

    const float* arow;
    {
        int m = m0 + lr;
        if (AMODE == 1) { int t = m / NB; int b = m - t * NB; arow = A + ((size_t)b * NT + t) * K; }
        else            { arow = A + (size_t)m * K; }
    }
    const float* wrow = W + (size_t)(n0 + lr) * K;

    float4 pa = *(const float4*)(arow + lf * 4);
    float4 pw = *(const float4*)(wrow + lf * 4);
    float acc[4][4] = {};

    for (int k0 = 0; k0 < K; k0 += 16) {
        As[lf*4+0][lr] = pa.x; As[lf*4+1][lr] = pa.y; As[lf*4+2][lr] = pa.z; As[lf*4+3][lr] = pa.w;
        Ws[lf*4+0][lr] = pw.x; Ws[lf*4+1][lr] = pw.y; Ws[lf*4+2][lr] = pw.z; Ws[lf*4+3][lr] = pw.w;
        __syncthreads();
        int kn = k0 + 16;
        if (kn < K) {
            pa = *(const float4*)(arow + kn + lf * 4);
            pw = *(const float4*)(wrow + kn + lf * 4);
        }
#pragma unroll
        for (int k = 0; k < 16; k++) {
            float4 av = *(const float4*)&As[k][ty * 4];
            float4 wv = *(const float4*)&Ws[k][tx * 4];
            fma16(acc, av, wv);
        }
        __syncthreads();
    }

    float4 bv = *(const float4*)&bias[n0 + tx * 4];
    float4 b2v = make_float4(0.f, 0.f, 0.f, 0.f);
    if (HB2) b2v = *(const float4*)&bias2[n0 + tx * 4];

#pragma unroll
    for (int i = 0; i < 4; i++) {
        int m = m0 + ty * 4 + i;
        bool zrow = false;
        if (MASKZ) zrow = (lens[m / NT] == 0);
        float4 r;
        r.x = acc[i][0] + bv.x + b2v.x; r.y = acc[i][1] + bv.y + b2v.y;
        r.z = acc[i][2] + bv.z + b2v.z; r.w = acc[i][3] + bv.w + b2v.w;
        if (RELU) { r.x = fmaxf(r.x, 0.f); r.y = fmaxf(r.y, 0.f); r.z = fmaxf(r.z, 0.f); r.w = fmaxf(r.w, 0.f); }
        if (MASKZ && zrow) { r.x = 0.f; r.y = 0.f; r.z = 0.f; r.w = 0.f; }
        *(float4*)&Cout[(size_t)m * N + n0 + tx * 4] = r;
    }
}

// ---------------- warp-MMA LSTM step kernel ----------------
// 64 CTAs x 256 thr. CTA owns 16 hidden units = 64 gate rows (unit-major: n = uu*4+g).
// C = [64 batch x 64 gate-rows]; warps 4(m) x 2(n), each m16n32 via 4x mma.m16n8k16.
// 3-term bf16 split: Ahi*Whi + Alo*Whi + Ahi*Wlo. K chunked by 64, cp.async double-buffered.
// smem stage: 4 parts (Ahi,Alo,Whi,Wlo), each 64 rows x 144B (72 bf16, padded) = 9216B; stage=36864B.
#define STAGE_BYTES 36864
#define STEP_SMEM (2 * STAGE_BYTES)

template<int LAYER>
__global__ void __launch_bounds__(256) step_mma_kernel(
    const int* __restrict__ lens, int t,
    const float* __restrict__ preb,   // layer0: pre0 base; layer1: b_ih1
    const float* __restrict__ bhh)    // layer1: b_hh1
{
    extern __shared__ char smem[];
    const uint32_t sb = smem_u32(smem);
    const int tid = threadIdx.x;
    const int lane = tid & 31, wid = tid >> 5;
    const int wm = wid & 3, wn = wid >> 2;
    const int blk = blockIdx.x;
    const int KW  = LAYER ? 2 * NH : NH;
    const int NCH = LAYER ? 32 : 16;
    const int ping = t & 1;

    const __nv_bfloat16* whi = (LAYER ? g_w1p[0] : g_w0p[0]) + (size_t)blk * 64 * KW;
    const __nv_bfloat16* wlo = (LAYER ? g_w1p[1] : g_w0p[1]) + (size_t)blk * 64 * KW;

    float d[4][4] = {};

    // ---- async load of one k64 chunk into stage stg ----
    auto issue_load = [&](int c, int stg) {
        uint32_t base = sb + (uint32_t)stg * STAGE_BYTES;
        const __nv_bfloat16* srcs[4];
        if (LAYER == 0) {
            srcs[0] = g_h0bf[ping][0] + c * 64;
            srcs[1] = g_h0bf[ping][1] + c * 64;
        } else {
            if (c < 16) { srcs[0] = g_h0in[0] + c * 64;            srcs[1] = g_h0in[1] + c * 64; }
            else        { srcs[0] = g_h1bf[ping][0] + (c-16)*64;   srcs[1] = g_h1bf[ping][1] + (c-16)*64; }
        }
        srcs[2] = whi + c * 64;
        srcs[3] = wlo + c * 64;
        int strides[4] = {NH, NH, KW, KW};
#pragma unroll
        for (int i = 0; i < 8; i++) {
            int s = tid + (i << 8);            // 0..2047
            int p = s >> 9, r = (s >> 3) & 63, seg = s & 7;
            const __nv_bfloat16* src = srcs[p] + (size_t)r * strides[p] + seg * 8;
            uint32_t dst = base + (uint32_t)(p * 9216 + r * 144 + seg * 16);
            cpa16(dst, src);
        }
        asm volatile("cp.async.commit_group;" ::: "memory");
    };

    issue_load(0, 0);

    const uint32_t a_off = (uint32_t)((wm * 16 + (lane & 15)) * 144 + (lane >> 4) * 16);
    const uint32_t w_off = (uint32_t)((wn * 32 + (lane & 7) + ((lane >> 4) << 3)) * 144
                                      + ((lane >> 3) & 1) * 16);

    for (int c = 0; c < NCH; c++) {
        if (c + 1 < NCH) {
            issue_load(c + 1, (c + 1) & 1);
            asm volatile("cp.async.wait_group 1;" ::: "memory");
        } else {
            asm volatile("cp.async.wait_group 0;" ::: "memory");
        }
        __syncthreads();

        uint32_t Ah = sb + (uint32_t)((c & 1) * STAGE_BYTES);
        uint32_t Al = Ah + 9216, Wh = Ah + 18432, Wl = Ah + 27648;
#pragma unroll
        for (int kq = 0; kq < 4; kq++) {
            uint32_t kb = (uint32_t)kq * 32;
            uint32_t ah[4], al[4], wh[8], wl[8];
            ldmx4(ah, Ah + a_off + kb);
            ldmx4(al, Al + a_off + kb);
            ldmx4(wh,     Wh + w_off + kb);
            ldmx4(wh + 4, Wh + w_off + 16 * 144 + kb);
            ldmx4(wl,     Wl + w_off + kb);
            ldmx4(wl + 4, Wl + w_off + 16 * 144 + kb);
            mma16816(d[0], ah, wh);     mma16816(d[1], ah, wh + 2);
            mma16816(d[2], ah, wh + 4); mma16816(d[3], ah, wh + 6);
            mma16816(d[0], al, wh);     mma16816(d[1], al, wh + 2);
            mma16816(d[2], al, wh + 4); mma16816(d[3], al, wh + 6);
            mma16816(d[0], ah, wl);     mma16816(d[1], ah, wl + 2);
            mma16816(d[2], ah, wl + 4); mma16816(d[3], ah, wl + 6);
        }
        __syncthreads();
    }

    // ---- register-only epilogue ----
    // thread's batch row: even lanes row (lane>>2), odd lanes row+8
    const int b = wm * 16 + (lane >> 2) + ((lane & 1) << 3);
    int L = lens[b]; if (L < 1) L = 1;
    const bool valid = (t < L);

    float* cptr = LAYER ? g_c1 : g_c0;
    float* hptr = LAYER ? g_h1f : g_h0f;
    __nv_bfloat16* nhi = (LAYER ? g_h1bf[ping ^ 1][0] : g_h0bf[ping ^ 1][0]);
    __nv_bfloat16* nlo = (LAYER ? g_h1bf[ping ^ 1][1] : g_h0bf[ping ^ 1][1]);

#pragma unroll
    for (int tt = 0; tt < 4; tt++) {
        // quad-pair exchange: gather all 4 gates of one (b,uu) cell per lane
        float s0 = (lane & 1) ? d[tt][0] : d[tt][2];
        float s1 = (lane & 1) ? d[tt][1] : d[tt][3];
        float r0 = __shfl_xor_sync(0xffffffffu, s0, 1);
        float r1 = __shfl_xor_sync(0xffffffffu, s1, 1);
        float q0, q1, q2, q3;
        if (lane & 1) { q2 = d[tt][2]; q3 = d[tt][3]; q0 = r0; q1 = r1; }
        else          { q0 = d[tt][0]; q1 = d[tt][1]; q2 = r0; q3 = r1; }

        int uu = wn * 8 + tt * 2 + ((lane & 3) >> 1);
        int u  = blk * 16 + uu;

        float p0, p1, p2, p3;
        if (LAYER == 0) {
            const float* p = preb + ((size_t)(t * NB + b)) * G4 + u;
            p0 = p[0]; p1 = p[NH]; p2 = p[2 * NH]; p3 = p[3 * NH];
        } else {
            p0 = preb[u]          + bhh[u];
            p1 = preb[NH + u]     + bhh[NH + u];
            p2 = preb[2 * NH + u] + bhh[2 * NH + u];
            p3 = preb[3 * NH + u] + bhh[3 * NH + u];
        }

        size_t off = (size_t)b * NH + u;
        float c_old = cptr[off], h_old = hptr[off];
        float iv = sigf(q0 + p0), fv = sigf(q1 + p1);
        float gv = tanhft(q2 + p2), ov = sigf(q3 + p3);
        float cn = fv * c_old + iv * gv;
        float hn = ov * tanhft(cn);
        float cws  = valid ? cn : c_old;
        float hcar = valid ? hn : h_old;
        float hin  = valid ? hn : 0.f;
        cptr[off] = cws;
        hptr[off] = hcar;
        __nv_bfloat16 hhi = __float2bfloat16(hcar);
        nhi[off] = hhi;
        nlo[off] = __float2bfloat16(hcar - __bfloat162float(hhi));
        if (LAYER == 0) {
            __nv_bfloat16 ihi = __float2bfloat16(hin);
            g_h0in[0][off] = ihi;
            g_h0in[1][off] = __float2bfloat16(hin - __bfloat162float(ihi));
        } else {
            g_lstm_out[((size_t)b * NT + t) * NH + u] = hin;
        }
    }
}

// ---------------- finalize hn / cn ----------------
__global__ void finalize_hc_kernel(float* __restrict__ hn, float* __restrict__ cn,
                                   const int* __restrict__ lens)
{
    int idx = blockIdx.x * 256 + threadIdx.x;   // < NL*NB*NH
    int l = idx >> 16;
    int r = idx & 65535;
    int b = r >> 10;
    bool z = (lens[b] == 0);
    hn[idx] = z ? 0.f : (l ? g_h1f[r] : g_h0f[r]);
    cn[idx] = z ? 0.f : (l ? g_c1[r]  : g_c0[r]);
}

// ---------------- entry point ----------------
extern "C" void kernel_launch(void* const* d_in, const int* in_sizes, int n_in,
                              void* d_out, int out_size)
{
    (void)in_sizes; (void)n_in; (void)out_size;
    const float* step_input = (const float*)d_in[0];
    const float* clstm      = (const float*)d_in[1];
    const float* hidden     = (const float*)d_in[2];
    const float* cell       = (const float*)d_in[3];
    const int* lens         = (const int*)d_in[4];
    const float* w_ih0 = (const float*)d_in[5];
    const float* w_hh0 = (const float*)d_in[6];
    const float* b_ih0 = (const float*)d_in[7];
    const float* b_hh0 = (const float*)d_in[8];
    const float* w_ih1 = (const float*)d_in[9];
    const float* w_hh1 = (const float*)d_in[10];
    const float* b_ih1 = (const float*)d_in[11];
    const float* b_hh1 = (const float*)d_in[12];
    const float* w1 = (const float*)d_in[13];
    const float* b1 = (const float*)d_in[14];
    const float* w2 = (const float*)d_in[15];
    const float* b2 = (const float*)d_in[16];

    float* out = (float*)d_out;
    float* out_logits = out;
    float* out_hn = out + (size_t)NB * NT * NO;
    float* out_cn = out_hn + (size_t)NL * NB * NH;

    float *pre0p, *loutp, *fc1p;
    cudaGetSymbolAddress((void**)&pre0p, g_pre0);
    cudaGetSymbolAddress((void**)&loutp, g_lstm_out);
    cudaGetSymbolAddress((void**)&fc1p, g_fc1);

    cudaFuncSetAttribute(step_mma_kernel<0>, cudaFuncAttributeMaxDynamicSharedMemorySize, STEP_SMEM);
    cudaFuncSetAttribute(step_mma_kernel<1>, cudaFuncAttributeMaxDynamicSharedMemorySize, STEP_SMEM);

    // 1) init state + weight prep
    init_state_kernel<<<NL * NB, 256>>>(clstm, hidden, cell, lens);
    prep_w0_kernel<<<4096, 256>>>(w_hh0);
    prep_w1_kernel<<<8192, 256>>>(w_ih1, w_hh1);

    // 2) pre0 = x @ Wih0^T + b_ih0 + b_hh0
    gemm64_kernel<1, false, false, true><<<dim3(G4 / 64, (NB * NT) / 64), 256>>>(
        step_input, w_ih0, b_ih0, b_hh0, pre0p, G4, NI, nullptr);

    // 3) sequential LSTM via warp MMA
    for (int t = 0; t < NT; t++) {
        step_mma_kernel<0><<<64, 256, STEP_SMEM>>>(lens, t, pre0p, nullptr);
        step_mma_kernel<1><<<64, 256, STEP_SMEM>>>(lens, t, b_ih1, b_hh1);
    }

    // 4) FC1
    gemm64_kernel<0, true, false, false><<<dim3(NH / 64, (NB * NT) / 64), 256>>>(
        loutp, w1, b1, nullptr, fc1p, NH, NH, nullptr);

    // 5) FC2 + zero-length masking
    gemm64_kernel<0, true, true, false><<<dim3(NO / 64, (NB * NT) / 64), 256>>>(
        fc1p, w2, b2, nullptr, out_logits, NO, NH, lens);

    // 6) hn / cn
    finalize_hc_kernel<<<(NL * NB * NH) / 256, 256>>>(out_hn, out_cn, lens);
}

// round 6
// speedup vs baseline: 1.3862x; 1.1096x over previous
#include <cuda_runtime.h>
#include <cuda_bf16.h>
#include <math.h>
#include <stdint.h>

#define NL 2
#define NB 64
#define NT 256
#define NI 512
#define NH 1024
#define NO 256
#define G4 4096
#define MROWS (NB*NT)   // 16384

// ---------------- scratch (device globals) ----------------
__device__ __align__(16) float g_pre0[(size_t)NT*NB*G4];   // [t][b][4H] fp32
__device__ __align__(16) float g_c0[NB*NH], g_c1[NB*NH];
__device__ __align__(16) float g_h0f[NB*NH], g_h1f[NB*NH];
__device__ __align__(16) __nv_bfloat16 g_h0bf[2][2][NB*NH];   // [ping][hi/lo]
__device__ __align__(16) __nv_bfloat16 g_h1bf[2][2][NB*NH];
__device__ __align__(16) __nv_bfloat16 g_h0in[2][NB*NH];      // [hi/lo] layer1 input
__device__ __align__(16) __nv_bfloat16 g_w0p[2][(size_t)G4*NH];     // reordered Whh0 hi/lo
__device__ __align__(16) __nv_bfloat16 g_w1p[2][(size_t)G4*2*NH];   // reordered [Wih1|Whh1] hi/lo
// big-GEMM operands (hi/lo bf16)
__device__ __align__(16) __nv_bfloat16 g_xbf[2][(size_t)MROWS*NI];      // x reordered rows m=t*64+b
__device__ __align__(16) __nv_bfloat16 g_wih0s[2][(size_t)G4*NI];
__device__ __align__(16) __nv_bfloat16 g_w1s[2][(size_t)NH*NH];
__device__ __align__(16) __nv_bfloat16 g_w2s[2][(size_t)NO*NH];
__device__ __align__(16) __nv_bfloat16 g_loutbf[2][(size_t)MROWS*NH];  // lstm_out rows m=b*256+t
__device__ __align__(16) __nv_bfloat16 g_fc1bf[2][(size_t)MROWS*NH];

// ---------------- low-level helpers ----------------
__device__ __forceinline__ uint32_t smem_u32(const void* p) {
    uint32_t a;
    asm("{ .reg .u64 t; cvta.to.shared.u64 t, %1; cvt.u32.u64 %0, t; }" : "=r"(a) : "l"(p));
    return a;
}
__device__ __forceinline__ void cpa16(uint32_t dst, const void* src) {
    asm volatile("cp.async.cg.shared.global [%0], [%1], 16;" :: "r"(dst), "l"(src) : "memory");
}
__device__ __forceinline__ void ldmx4(uint32_t* r, uint32_t addr) {
    asm volatile("ldmatrix.sync.aligned.m8n8.x4.shared.b16 {%0,%1,%2,%3}, [%4];"
                 : "=r"(r[0]), "=r"(r[1]), "=r"(r[2]), "=r"(r[3]) : "r"(addr));
}
__device__ __forceinline__ void mma16816(float (&d)[4], const uint32_t* a, const uint32_t* b) {
    asm volatile("mma.sync.aligned.m16n8k16.row.col.f32.bf16.bf16.f32 "
        "{%0,%1,%2,%3}, {%4,%5,%6,%7}, {%8,%9}, {%0,%1,%2,%3};"
        : "+f"(d[0]), "+f"(d[1]), "+f"(d[2]), "+f"(d[3])
        : "r"(a[0]), "r"(a[1]), "r"(a[2]), "r"(a[3]), "r"(b[0]), "r"(b[1]));
}
__device__ __forceinline__ float sigf(float x)  { return 1.f / (1.f + __expf(-x)); }
__device__ __forceinline__ float tanhft(float x){ return 2.f / (1.f + __expf(-2.f * x)) - 1.f; }

// ---------------- init: weighted hidden + cell copy + bf16 state ----------------
__global__ void init_state_kernel(const float* __restrict__ clstm,
                                  const float* __restrict__ hidden,
                                  const float* __restrict__ cell,
                                  const int* __restrict__ lens)
{
    int l = blockIdx.x >> 6;
    int b = blockIdx.x & 63;
    const float* cl = clstm + (size_t)b * NH;
    const float* hd = hidden + ((size_t)l * NB + b) * NH;
    const float* ce = cell   + ((size_t)l * NB + b) * NH;

    float cmn = 3.4e38f, cmx = -3.4e38f, hmn = 3.4e38f, hmx = -3.4e38f;
    for (int h = threadIdx.x; h < NH; h += 256) {
        float cv = cl[h], hv = hd[h];
        cmn = fminf(cmn, cv); cmx = fmaxf(cmx, cv);
        hmn = fminf(hmn, hv); hmx = fmaxf(hmx, hv);
    }
#pragma unroll
    for (int o = 16; o; o >>= 1) {
        cmn = fminf(cmn, __shfl_xor_sync(0xffffffffu, cmn, o));
        cmx = fmaxf(cmx, __shfl_xor_sync(0xffffffffu, cmx, o));
        hmn = fminf(hmn, __shfl_xor_sync(0xffffffffu, hmn, o));
        hmx = fmaxf(hmx, __shfl_xor_sync(0xffffffffu, hmx, o));
    }
    __shared__ float s[4][8];
    __shared__ float fs[4];
    int w = threadIdx.x >> 5, ln = threadIdx.x & 31;
    if (ln == 0) { s[0][w] = cmn; s[1][w] = cmx; s[2][w] = hmn; s[3][w] = hmx; }
    __syncthreads();
    if (threadIdx.x < 4) {
        float v = s[threadIdx.x][0];
        bool ismin = (threadIdx.x == 0) || (threadIdx.x == 2);
#pragma unroll
        for (int i = 1; i < 8; i++) {
            float x = s[threadIdx.x][i];
            v = ismin ? fminf(v, x) : fmaxf(v, x);
        }
        fs[threadIdx.x] = v;
    }
    __syncthreads();
    cmn = fs[0]; cmx = fs[1]; hmn = fs[2]; hmx = fs[3];
    float crange = cmx - cmn, hrange = hmx - hmn;
    bool lz = (lens[b] == 0);

    float* hf = l ? g_h1f : g_h0f;
    float* cf = l ? g_c1  : g_c0;
    __nv_bfloat16* bhi = l ? g_h1bf[0][0] : g_h0bf[0][0];
    __nv_bfloat16* blo = l ? g_h1bf[0][1] : g_h0bf[0][1];

    for (int h = threadIdx.x; h < NH; h += 256) {
        float cv = cl[h], hv = hd[h];
        float s1 = (crange > 0.f) ? (cv - cmn) / crange : cv;
        float s2 = (hrange > 0.f) ? (hmn + s1 * hrange) : s1;
        float c  = lz ? cv : s2;
        float hw = 0.5f * hv + 0.5f * c;
        size_t off = (size_t)b * NH + h;
        hf[off] = hw;
        cf[off] = ce[h];
        __nv_bfloat16 hi = __float2bfloat16(hw);
        bhi[off] = hi;
        blo[off] = __float2bfloat16(hw - __bfloat162float(hi));
    }
}

// ---------------- weight prep for step kernels: unit-major reorder + hi/lo split ----------------
__global__ void prep_w0_kernel(const float* __restrict__ w)
{
    int idx = blockIdx.x * 256 + threadIdx.x;
    int k = (idx & 255) * 4;
    int row = idx >> 8;
    int blk = row >> 6, r = row & 63;
    int uu = r >> 2, g = r & 3;
    int srow = g * NH + blk * 16 + uu;
    float4 v = *(const float4*)(w + (size_t)srow * NH + k);
    size_t o = (size_t)row * NH + k;
    float vv[4] = {v.x, v.y, v.z, v.w};
#pragma unroll
    for (int i = 0; i < 4; i++) {
        __nv_bfloat16 hi = __float2bfloat16(vv[i]);
        g_w0p[0][o + i] = hi;
        g_w0p[1][o + i] = __float2bfloat16(vv[i] - __bfloat162float(hi));
    }
}

__global__ void prep_w1_kernel(const float* __restrict__ wih, const float* __restrict__ whh)
{
    int idx = blockIdx.x * 256 + threadIdx.x;
    int k = (idx & 511) * 4;
    int row = idx >> 9;
    int blk = row >> 6, r = row & 63;
    int uu = r >> 2, g = r & 3;
    int srow = g * NH + blk * 16 + uu;
    const float* src = (k < NH) ? (wih + (size_t)srow * NH + k)
                                : (whh + (size_t)srow * NH + (k - NH));
    float4 v = *(const float4*)src;
    size_t o = (size_t)row * (2 * NH) + k;
    float vv[4] = {v.x, v.y, v.z, v.w};
#pragma unroll
    for (int i = 0; i < 4; i++) {
        __nv_bfloat16 hi = __float2bfloat16(vv[i]);
        g_w1p[0][o + i] = hi;
        g_w1p[1][o + i] = __float2bfloat16(vv[i] - __bfloat162float(hi));
    }
}

// ---------------- generic fp32 -> bf16 hi/lo split (plain layout) ----------------
__global__ void conv_split_kernel(const float* __restrict__ src,
                                  __nv_bfloat16* __restrict__ hi,
                                  __nv_bfloat16* __restrict__ lo)
{
    size_t i = ((size_t)blockIdx.x * 256 + threadIdx.x) * 4;
    float4 v = *(const float4*)(src + i);
    float vv[4] = {v.x, v.y, v.z, v.w};
#pragma unroll
    for (int j = 0; j < 4; j++) {
        __nv_bfloat16 h = __float2bfloat16(vv[j]);
        hi[i + j] = h;
        lo[i + j] = __float2bfloat16(vv[j] - __bfloat162float(h));
    }
}

// ---------------- x conversion with reorder: row m = t*64+b  <-  x[b][t][:] ----------------
__global__ void conv_x_kernel(const float* __restrict__ x)
{
    int idx = blockIdx.x * 256 + threadIdx.x;    // 2,097,152 threads
    int kq = idx & 127;                          // 128 float4 per row
    int m = idx >> 7;
    int t = m >> 6, b = m & 63;
    float4 v = *(const float4*)(x + ((size_t)b * NT + t) * NI + kq * 4);
    size_t o = (size_t)m * NI + kq * 4;
    float vv[4] = {v.x, v.y, v.z, v.w};
#pragma unroll
    for (int j = 0; j < 4; j++) {
        __nv_bfloat16 h = __float2bfloat16(vv[j]);
        g_xbf[0][o + j] = h;
        g_xbf[1][o + j] = __float2bfloat16(vv[j] - __bfloat162float(h));
    }
}

// ---------------- big MMA GEMM: C[m][n] = A(m,:)·W(n,:)^T, bf16 3-term split ----------------
// BM=128, BN=128, BK=32; 256 thr; warps 4(m)x2(n), warp tile m32 x n64.
// smem stage: Ahi,Alo,Whi,Wlo each 128 rows x 80B (32 bf16 + pad) = 10240B; stage 40960B; 2 stages.
// EP: 0 = pre0 (+bias+bias2, fp32 out), 1 = FC1 (relu, hi/lo bf16 out), 2 = FC2 (relu, maskz, fp32 out)
#define GSTAGE 40960
#define GEMM_SMEM (2*GSTAGE)

template<int EP>
__global__ void __launch_bounds__(256) mma_gemm_kernel(
    const __nv_bfloat16* __restrict__ Ahi, const __nv_bfloat16* __restrict__ Alo,
    const __nv_bfloat16* __restrict__ Whi, const __nv_bfloat16* __restrict__ Wlo,
    const float* __restrict__ bias, const float* __restrict__ bias2,
    float* __restrict__ Cf,
    __nv_bfloat16* __restrict__ Chi, __nv_bfloat16* __restrict__ Clo,
    int N, int K, const int* __restrict__ lens)
{
    extern __shared__ char smem[];
    const uint32_t sb = smem_u32(smem);
    const int tid = threadIdx.x;
    const int lane = tid & 31, wid = tid >> 5;
    const int wm = wid & 3, wn = wid >> 2;
    const int n0 = blockIdx.x * 128;
    const int m0 = blockIdx.y * 128;
    const int KC = K >> 5;

    // per-thread cp.async decode (8 transfers/stage)
    const int p_   = tid >> 6 >> 1;              // unused placeholder (kept simple below)
    (void)p_;

    float acc[2][8][4] = {};

    auto issue_load = [&](int c, int stg) {
        const int k0 = c << 5;
        uint32_t base = sb + (uint32_t)stg * GSTAGE;
#pragma unroll
        for (int i = 0; i < 8; i++) {
            int s = tid + (i << 8);
            int p = s >> 9;                       // 0..3
            int r = (s >> 2) & 127;
            int seg = s & 3;
            const __nv_bfloat16* src;
            if (p == 0)      src = Ahi + (size_t)(m0 + r) * K + k0 + seg * 8;
            else if (p == 1) src = Alo + (size_t)(m0 + r) * K + k0 + seg * 8;
            else if (p == 2) src = Whi + (size_t)(n0 + r) * K + k0 + seg * 8;
            else             src = Wlo + (size_t)(n0 + r) * K + k0 + seg * 8;
            cpa16(base + (uint32_t)(p * 10240 + r * 80 + seg * 16), src);
        }
        asm volatile("cp.async.commit_group;" ::: "memory");
    };

    issue_load(0, 0);

    const uint32_t a_base = (uint32_t)((wm * 32 + (lane & 15)) * 80 + (lane >> 4) * 16);
    const uint32_t w_base = (uint32_t)((wn * 64 + (lane & 7) + ((lane >> 4) << 3)) * 80
                                       + ((lane >> 3) & 1) * 16);

    for (int c = 0; c < KC; c++) {
        if (c + 1 < KC) {
            issue_load(c + 1, (c + 1) & 1);
            asm volatile("cp.async.wait_group 1;" ::: "memory");
        } else {
            asm volatile("cp.async.wait_group 0;" ::: "memory");
        }
        __syncthreads();

        uint32_t Ah = sb + (uint32_t)((c & 1) * GSTAGE);
        uint32_t Al = Ah + 10240, Wh = Ah + 20480, Wl = Ah + 30720;
#pragma unroll
        for (int kk = 0; kk < 2; kk++) {
            uint32_t kb = (uint32_t)kk * 32;
            uint32_t ah[2][4], al[2][4], wh[16], wl[16];
#pragma unroll
            for (int sub = 0; sub < 2; sub++) {
                ldmx4(ah[sub], Ah + a_base + sub * 16 * 80 + kb);
                ldmx4(al[sub], Al + a_base + sub * 16 * 80 + kb);
            }
#pragma unroll
            for (int q = 0; q < 4; q++) {
                ldmx4(wh + q * 4, Wh + w_base + q * 16 * 80 + kb);
                ldmx4(wl + q * 4, Wl + w_base + q * 16 * 80 + kb);
            }
#pragma unroll
            for (int sub = 0; sub < 2; sub++) {
#pragma unroll
                for (int nq = 0; nq < 8; nq++) {
                    mma16816(acc[sub][nq], ah[sub], wh + nq * 2);
                    mma16816(acc[sub][nq], al[sub], wh + nq * 2);
                    mma16816(acc[sub][nq], ah[sub], wl + nq * 2);
                }
            }
        }
        __syncthreads();
    }

    // ---- epilogue ----
#pragma unroll
    for (int sub = 0; sub < 2; sub++) {
        int r0 = m0 + wm * 32 + sub * 16 + (lane >> 2);
#pragma unroll
        for (int nq = 0; nq < 8; nq++) {
            int c0 = n0 + wn * 64 + nq * 8 + (lane & 3) * 2;
            float b0 = bias[c0], b1 = bias[c0 + 1];
            if (EP == 0) { b0 += bias2[c0]; b1 += bias2[c0 + 1]; }
#pragma unroll
            for (int half = 0; half < 2; half++) {
                int r = r0 + half * 8;
                float v0 = acc[sub][nq][half * 2]     + b0;
                float v1 = acc[sub][nq][half * 2 + 1] + b1;
                if (EP >= 1) { v0 = fmaxf(v0, 0.f); v1 = fmaxf(v1, 0.f); }
                if (EP == 2) {
                    if (lens[r >> 8] == 0) { v0 = 0.f; v1 = 0.f; }
                }
                if (EP == 1) {
                    __nv_bfloat16 h0 = __float2bfloat16(v0);
                    __nv_bfloat16 h1 = __float2bfloat16(v1);
                    __nv_bfloat162 hp; hp.x = h0; hp.y = h1;
                    __nv_bfloat162 lp;
                    lp.x = __float2bfloat16(v0 - __bfloat162float(h0));
                    lp.y = __float2bfloat16(v1 - __bfloat162float(h1));
                    *(__nv_bfloat162*)&Chi[(size_t)r * N + c0] = hp;
                    *(__nv_bfloat162*)&Clo[(size_t)r * N + c0] = lp;
                } else {
                    float2 o; o.x = v0; o.y = v1;
                    *(float2*)&Cf[(size_t)r * N + c0] = o;
                }
            }
        }
    }
}

// ---------------- warp-MMA LSTM step kernel (unchanged core from R5) ----------------
#define STAGE_BYTES 36864
#define STEP_SMEM (2 * STAGE_BYTES)

template<int LAYER>
__global__ void __launch_bounds__(256) step_mma_kernel(
    const int* __restrict__ lens, int t,
    const float* __restrict__ preb,   // layer0: pre0 base; layer1: b_ih1
    const float* __restrict__ bhh)    // layer1: b_hh1
{
    extern __shared__ char smem[];
    const uint32_t sb = smem_u32(smem);
    const int tid = threadIdx.x;
    const int lane = tid & 31, wid = tid >> 5;
    const int wm = wid & 3, wn = wid >> 2;
    const int blk = blockIdx.x;
    const int KW  = LAYER ? 2 * NH : NH;
    const int NCH = LAYER ? 32 : 16;
    const int ping = t & 1;

    const __nv_bfloat16* whi = (LAYER ? g_w1p[0] : g_w0p[0]) + (size_t)blk * 64 * KW;
    const __nv_bfloat16* wlo = (LAYER ? g_w1p[1] : g_w0p[1]) + (size_t)blk * 64 * KW;

    float d[4][4] = {};

    auto issue_load = [&](int c, int stg) {
        uint32_t base = sb + (uint32_t)stg * STAGE_BYTES;
        const __nv_bfloat16* srcs[4];
        if (LAYER == 0) {
            srcs[0] = g_h0bf[ping][0] + c * 64;
            srcs[1] = g_h0bf[ping][1] + c * 64;
        } else {
            if (c < 16) { srcs[0] = g_h0in[0] + c * 64;            srcs[1] = g_h0in[1] + c * 64; }
            else        { srcs[0] = g_h1bf[ping][0] + (c-16)*64;   srcs[1] = g_h1bf[ping][1] + (c-16)*64; }
        }
        srcs[2] = whi + c * 64;
        srcs[3] = wlo + c * 64;
        int strides[4] = {NH, NH, KW, KW};
#pragma unroll
        for (int i = 0; i < 8; i++) {
            int s = tid + (i << 8);
            int p = s >> 9, r = (s >> 3) & 63, seg = s & 7;
            const __nv_bfloat16* src = srcs[p] + (size_t)r * strides[p] + seg * 8;
            uint32_t dst = base + (uint32_t)(p * 9216 + r * 144 + seg * 16);
            cpa16(dst, src);
        }
        asm volatile("cp.async.commit_group;" ::: "memory");
    };

    issue_load(0, 0);

    const uint32_t a_off = (uint32_t)((wm * 16 + (lane & 15)) * 144 + (lane >> 4) * 16);
    const uint32_t w_off = (uint32_t)((wn * 32 + (lane & 7) + ((lane >> 4) << 3)) * 144
                                      + ((lane >> 3) & 1) * 16);

    for (int c = 0; c < NCH; c++) {
        if (c + 1 < NCH) {
            issue_load(c + 1, (c + 1) & 1);
            asm volatile("cp.async.wait_group 1;" ::: "memory");
        } else {
            asm volatile("cp.async.wait_group 0;" ::: "memory");
        }
        __syncthreads();

        uint32_t Ah = sb + (uint32_t)((c & 1) * STAGE_BYTES);
        uint32_t Al = Ah + 9216, Wh = Ah + 18432, Wl = Ah + 27648;
#pragma unroll
        for (int kq = 0; kq < 4; kq++) {
            uint32_t kb = (uint32_t)kq * 32;
            uint32_t ah[4], al[4], wh[8], wl[8];
            ldmx4(ah, Ah + a_off + kb);
            ldmx4(al, Al + a_off + kb);
            ldmx4(wh,     Wh + w_off + kb);
            ldmx4(wh + 4, Wh + w_off + 16 * 144 + kb);
            ldmx4(wl,     Wl + w_off + kb);
            ldmx4(wl + 4, Wl + w_off + 16 * 144 + kb);
            mma16816(d[0], ah, wh);     mma16816(d[1], ah, wh + 2);
            mma16816(d[2], ah, wh + 4); mma16816(d[3], ah, wh + 6);
            mma16816(d[0], al, wh);     mma16816(d[1], al, wh + 2);
            mma16816(d[2], al, wh + 4); mma16816(d[3], al, wh + 6);
            mma16816(d[0], ah, wl);     mma16816(d[1], ah, wl + 2);
            mma16816(d[2], ah, wl + 4); mma16816(d[3], ah, wl + 6);
        }
        __syncthreads();
    }

    const int b = wm * 16 + (lane >> 2) + ((lane & 1) << 3);
    int L = lens[b]; if (L < 1) L = 1;
    const bool valid = (t < L);

    float* cptr = LAYER ? g_c1 : g_c0;
    float* hptr = LAYER ? g_h1f : g_h0f;
    __nv_bfloat16* nhi = (LAYER ? g_h1bf[ping ^ 1][0] : g_h0bf[ping ^ 1][0]);
    __nv_bfloat16* nlo = (LAYER ? g_h1bf[ping ^ 1][1] : g_h0bf[ping ^ 1][1]);

#pragma unroll
    for (int tt = 0; tt < 4; tt++) {
        float s0 = (lane & 1) ? d[tt][0] : d[tt][2];
        float s1 = (lane & 1) ? d[tt][1] : d[tt][3];
        float r0 = __shfl_xor_sync(0xffffffffu, s0, 1);
        float r1 = __shfl_xor_sync(0xffffffffu, s1, 1);
        float q0, q1, q2, q3;
        if (lane & 1) { q2 = d[tt][2]; q3 = d[tt][3]; q0 = r0; q1 = r1; }
        else          { q0 = d[tt][0]; q1 = d[tt][1]; q2 = r0; q3 = r1; }

        int uu = wn * 8 + tt * 2 + ((lane & 3) >> 1);
        int u  = blk * 16 + uu;

        float p0, p1, p2, p3;
        if (LAYER == 0) {
            const float* p = preb + ((size_t)(t * NB + b)) * G4 + u;
            p0 = p[0]; p1 = p[NH]; p2 = p[2 * NH]; p3 = p[3 * NH];
        } else {
            p0 = preb[u]          + bhh[u];
            p1 = preb[NH + u]     + bhh[NH + u];
            p2 = preb[2 * NH + u] + bhh[2 * NH + u];
            p3 = preb[3 * NH + u] + bhh[3 * NH + u];
        }

        size_t off = (size_t)b * NH + u;
        float c_old = cptr[off], h_old = hptr[off];
        float iv = sigf(q0 + p0), fv = sigf(q1 + p1);
        float gv = tanhft(q2 + p2), ov = sigf(q3 + p3);
        float cn = fv * c_old + iv * gv;
        float hn = ov * tanhft(cn);
        float cws  = valid ? cn : c_old;
        float hcar = valid ? hn : h_old;
        float hin  = valid ? hn : 0.f;
        cptr[off] = cws;
        hptr[off] = hcar;
        __nv_bfloat16 hhi = __float2bfloat16(hcar);
        nhi[off] = hhi;
        nlo[off] = __float2bfloat16(hcar - __bfloat162float(hhi));
        if (LAYER == 0) {
            __nv_bfloat16 ihi = __float2bfloat16(hin);
            g_h0in[0][off] = ihi;
            g_h0in[1][off] = __float2bfloat16(hin - __bfloat162float(ihi));
        } else {
            size_t om = ((size_t)b * NT + t) * NH + u;
            __nv_bfloat16 ohi = __float2bfloat16(hin);
            g_loutbf[0][om] = ohi;
            g_loutbf[1][om] = __float2bfloat16(hin - __bfloat162float(ohi));
        }
    }
}

// ---------------- finalize hn / cn ----------------
__global__ void finalize_hc_kernel(float* __restrict__ hn, float* __restrict__ cn,
                                   const int* __restrict__ lens)
{
    int idx = blockIdx.x * 256 + threadIdx.x;
    int l = idx >> 16;
    int r = idx & 65535;
    int b = r >> 10;
    bool z = (lens[b] == 0);
    hn[idx] = z ? 0.f : (l ? g_h1f[r] : g_h0f[r]);
    cn[idx] = z ? 0.f : (l ? g_c1[r]  : g_c0[r]);
}

// ---------------- entry point ----------------
extern "C" void kernel_launch(void* const* d_in, const int* in_sizes, int n_in,
                              void* d_out, int out_size)
{
    (void)in_sizes; (void)n_in; (void)out_size;
    const float* step_input = (const float*)d_in[0];
    const float* clstm      = (const float*)d_in[1];
    const float* hidden     = (const float*)d_in[2];
    const float* cell       = (const float*)d_in[3];
    const int* lens         = (const int*)d_in[4];
    const float* w_ih0 = (const float*)d_in[5];
    const float* w_hh0 = (const float*)d_in[6];
    const float* b_ih0 = (const float*)d_in[7];
    const float* b_hh0 = (const float*)d_in[8];
    const float* w_ih1 = (const float*)d_in[9];
    const float* w_hh1 = (const float*)d_in[10];
    const float* b_ih1 = (const float*)d_in[11];
    const float* b_hh1 = (const float*)d_in[12];
    const float* w1 = (const float*)d_in[13];
    const float* b1 = (const float*)d_in[14];
    const float* w2 = (const float*)d_in[15];
    const float* b2 = (const float*)d_in[16];

    float* out = (float*)d_out;
    float* out_logits = out;
    float* out_hn = out + (size_t)NB * NT * NO;
    float* out_cn = out_hn + (size_t)NL * NB * NH;

    float* pre0p;
    cudaGetSymbolAddress((void**)&pre0p, g_pre0);
    __nv_bfloat16 *xbfp, *wih0sp, *w1sp, *w2sp, *loutp, *fc1p;
    cudaGetSymbolAddress((void**)&xbfp,   g_xbf);
    cudaGetSymbolAddress((void**)&wih0sp, g_wih0s);
    cudaGetSymbolAddress((void**)&w1sp,   g_w1s);
    cudaGetSymbolAddress((void**)&w2sp,   g_w2s);
    cudaGetSymbolAddress((void**)&loutp,  g_loutbf);
    cudaGetSymbolAddress((void**)&fc1p,   g_fc1bf);
    const size_t XSZ = (size_t)MROWS * NI;
    const size_t WIH0SZ = (size_t)G4 * NI;
    const size_t W1SZ = (size_t)NH * NH;
    const size_t W2SZ = (size_t)NO * NH;
    const size_t LSZ = (size_t)MROWS * NH;

    cudaFuncSetAttribute(step_mma_kernel<0>, cudaFuncAttributeMaxDynamicSharedMemorySize, STEP_SMEM);
    cudaFuncSetAttribute(step_mma_kernel<1>, cudaFuncAttributeMaxDynamicSharedMemorySize, STEP_SMEM);
    cudaFuncSetAttribute(mma_gemm_kernel<0>, cudaFuncAttributeMaxDynamicSharedMemorySize, GEMM_SMEM);
    cudaFuncSetAttribute(mma_gemm_kernel<1>, cudaFuncAttributeMaxDynamicSharedMemorySize, GEMM_SMEM);
    cudaFuncSetAttribute(mma_gemm_kernel<2>, cudaFuncAttributeMaxDynamicSharedMemorySize, GEMM_SMEM);

    // 1) init state + weight/input prep
    init_state_kernel<<<NL * NB, 256>>>(clstm, hidden, cell, lens);
    prep_w0_kernel<<<4096, 256>>>(w_hh0);
    prep_w1_kernel<<<8192, 256>>>(w_ih1, w_hh1);
    conv_x_kernel<<<8192, 256>>>(step_input);
    conv_split_kernel<<<(int)(WIH0SZ / 1024), 256>>>(w_ih0, wih0sp, wih0sp + WIH0SZ);
    conv_split_kernel<<<(int)(W1SZ / 1024), 256>>>(w1, w1sp, w1sp + W1SZ);
    conv_split_kernel<<<(int)(W2SZ / 1024), 256>>>(w2, w2sp, w2sp + W2SZ);

    // 2) pre0 = x @ Wih0^T + b_ih0 + b_hh0   (M=16384 rows m=t*64+b, N=4096, K=512)
    mma_gemm_kernel<0><<<dim3(G4 / 128, MROWS / 128), 256, GEMM_SMEM>>>(
        xbfp, xbfp + XSZ, wih0sp, wih0sp + WIH0SZ, b_ih0, b_hh0,
        pre0p, nullptr, nullptr, G4, NI, nullptr);

    // 3) sequential LSTM via warp MMA
    for (int t = 0; t < NT; t++) {
        step_mma_kernel<0><<<64, 256, STEP_SMEM>>>(lens, t, pre0p, nullptr);
        step_mma_kernel<1><<<64, 256, STEP_SMEM>>>(lens, t, b_ih1, b_hh1);
    }

    // 4) FC1: relu(lstm_out @ w1^T + b1) -> hi/lo bf16
    mma_gemm_kernel<1><<<dim3(NH / 128, MROWS / 128), 256, GEMM_SMEM>>>(
        loutp, loutp + LSZ, w1sp, w1sp + W1SZ, b1, nullptr,
        nullptr, fc1p, fc1p + LSZ, NH, NH, nullptr);

    // 5) FC2: relu(fc1 @ w2^T + b2), zero-length masked, fp32 out
    mma_gemm_kernel<2><<<dim3(NO / 128, MROWS / 128), 256, GEMM_SMEM>>>(
        fc1p, fc1p + LSZ, w2sp, w2sp + W2SZ, b2, nullptr,
        out_logits, nullptr, nullptr, NO, NH, lens);

    // 6) hn / cn
    finalize_hc_kernel<<<(NL * NB * NH) / 256, 256>>>(out_hn, out_cn, lens);
}

// round 7
// speedup vs baseline: 2.1917x; 1.5811x over previous
#include <cuda_runtime.h>
#include <cuda_bf16.h>
#include <math.h>
#include <stdint.h>

#define NL 2
#define NB 64
#define NT 256
#define NI 512
#define NH 1024
#define NO 256
#define G4 4096
#define MROWS (NB*NT)   // 16384
#define NCTA 128

// ---------------- scratch (device globals) ----------------
__device__ __align__(16) float g_pre0[(size_t)NT*NB*G4];   // [t][b][4H] fp32
__device__ __align__(16) float g_c0[NB*NH], g_c1[NB*NH];
__device__ __align__(16) float g_h0f[NB*NH], g_h1f[NB*NH];
__device__ __align__(16) __nv_bfloat16 g_h0bf[2][2][NB*NH];   // [ping][hi/lo]
__device__ __align__(16) __nv_bfloat16 g_h1bf[2][2][NB*NH];
__device__ __align__(16) __nv_bfloat16 g_h0in[2][NB*NH];      // [hi/lo] layer1 input
__device__ __align__(16) __nv_bfloat16 g_w0p[2][(size_t)G4*NH];     // reordered Whh0 hi/lo
__device__ __align__(16) __nv_bfloat16 g_w1p[2][(size_t)G4*2*NH];   // reordered [Wih1|Whh1] hi/lo
// big-GEMM operands (hi/lo bf16)
__device__ __align__(16) __nv_bfloat16 g_xbf[2][(size_t)MROWS*NI];
__device__ __align__(16) __nv_bfloat16 g_wih0s[2][(size_t)G4*NI];
__device__ __align__(16) __nv_bfloat16 g_w1s[2][(size_t)NH*NH];
__device__ __align__(16) __nv_bfloat16 g_w2s[2][(size_t)NO*NH];
__device__ __align__(16) __nv_bfloat16 g_loutbf[2][(size_t)MROWS*NH];  // rows m=b*256+t
__device__ __align__(16) __nv_bfloat16 g_fc1bf[2][(size_t)MROWS*NH];
// global barrier state
__device__ unsigned g_gen = 0;
__device__ unsigned g_cnt = 0;

// ---------------- low-level helpers ----------------
__device__ __forceinline__ uint32_t smem_u32(const void* p) {
    uint32_t a;
    asm("{ .reg .u64 t; cvta.to.shared.u64 t, %1; cvt.u32.u64 %0, t; }" : "=r"(a) : "l"(p));
    return a;
}
__device__ __forceinline__ void cpa16(uint32_t dst, const void* src) {
    asm volatile("cp.async.cg.shared.global [%0], [%1], 16;" :: "r"(dst), "l"(src) : "memory");
}
__device__ __forceinline__ void ldmx4(uint32_t* r, uint32_t addr) {
    asm volatile("ldmatrix.sync.aligned.m8n8.x4.shared.b16 {%0,%1,%2,%3}, [%4];"
                 : "=r"(r[0]), "=r"(r[1]), "=r"(r[2]), "=r"(r[3]) : "r"(addr));
}
__device__ __forceinline__ void mma16816(float (&d)[4], const uint32_t* a, const uint32_t* b) {
    asm volatile("mma.sync.aligned.m16n8k16.row.col.f32.bf16.bf16.f32 "
        "{%0,%1,%2,%3}, {%4,%5,%6,%7}, {%8,%9}, {%0,%1,%2,%3};"
        : "+f"(d[0]), "+f"(d[1]), "+f"(d[2]), "+f"(d[3])
        : "r"(a[0]), "r"(a[1]), "r"(a[2]), "r"(a[3]), "r"(b[0]), "r"(b[1]));
}
__device__ __forceinline__ float sigf(float x)  { return 1.f / (1.f + __expf(-x)); }
__device__ __forceinline__ float tanhft(float x){ return 2.f / (1.f + __expf(-2.f * x)) - 1.f; }

__device__ __forceinline__ unsigned ld_acq(const unsigned* p) {
    unsigned v;
    asm volatile("ld.acquire.gpu.global.u32 %0, [%1];" : "=r"(v) : "l"(p) : "memory");
    return v;
}
// sense-free generation barrier; all NCTA CTAs resident
__device__ __forceinline__ void gbar() {
    __syncthreads();
    if (threadIdx.x == 0) {
        unsigned old = ld_acq(&g_gen);
        __threadfence();
        unsigned arr = atomicAdd(&g_cnt, 1u);
        if (arr == NCTA - 1) {
            g_cnt = 0;
            __threadfence();
            atomicAdd(&g_gen, 1u);
        } else {
            while (ld_acq(&g_gen) == old) {}
        }
        __threadfence();
    }
    __syncthreads();
}

// ---------------- init: weighted hidden + cell copy + bf16 state ----------------
__global__ void init_state_kernel(const float* __restrict__ clstm,
                                  const float* __restrict__ hidden,
                                  const float* __restrict__ cell,
                                  const int* __restrict__ lens)
{
    int l = blockIdx.x >> 6;
    int b = blockIdx.x & 63;
    const float* cl = clstm + (size_t)b * NH;
    const float* hd = hidden + ((size_t)l * NB + b) * NH;
    const float* ce = cell   + ((size_t)l * NB + b) * NH;

    float cmn = 3.4e38f, cmx = -3.4e38f, hmn = 3.4e38f, hmx = -3.4e38f;
    for (int h = threadIdx.x; h < NH; h += 256) {
        float cv = cl[h], hv = hd[h];
        cmn = fminf(cmn, cv); cmx = fmaxf(cmx, cv);
        hmn = fminf(hmn, hv); hmx = fmaxf(hmx, hv);
    }
#pragma unroll
    for (int o = 16; o; o >>= 1) {
        cmn = fminf(cmn, __shfl_xor_sync(0xffffffffu, cmn, o));
        cmx = fmaxf(cmx, __shfl_xor_sync(0xffffffffu, cmx, o));
        hmn = fminf(hmn, __shfl_xor_sync(0xffffffffu, hmn, o));
        hmx = fmaxf(hmx, __shfl_xor_sync(0xffffffffu, hmx, o));
    }
    __shared__ float s[4][8];
    __shared__ float fs[4];
    int w = threadIdx.x >> 5, ln = threadIdx.x & 31;
    if (ln == 0) { s[0][w] = cmn; s[1][w] = cmx; s[2][w] = hmn; s[3][w] = hmx; }
    __syncthreads();
    if (threadIdx.x < 4) {
        float v = s[threadIdx.x][0];
        bool ismin = (threadIdx.x == 0) || (threadIdx.x == 2);
#pragma unroll
        for (int i = 1; i < 8; i++) {
            float x = s[threadIdx.x][i];
            v = ismin ? fminf(v, x) : fmaxf(v, x);
        }
        fs[threadIdx.x] = v;
    }
    __syncthreads();
    cmn = fs[0]; cmx = fs[1]; hmn = fs[2]; hmx = fs[3];
    float crange = cmx - cmn, hrange = hmx - hmn;
    bool lz = (lens[b] == 0);

    float* hf = l ? g_h1f : g_h0f;
    float* cf = l ? g_c1  : g_c0;
    __nv_bfloat16* bhi = l ? g_h1bf[0][0] : g_h0bf[0][0];
    __nv_bfloat16* blo = l ? g_h1bf[0][1] : g_h0bf[0][1];

    for (int h = threadIdx.x; h < NH; h += 256) {
        float cv = cl[h], hv = hd[h];
        float s1 = (crange > 0.f) ? (cv - cmn) / crange : cv;
        float s2 = (hrange > 0.f) ? (hmn + s1 * hrange) : s1;
        float c  = lz ? cv : s2;
        float hw = 0.5f * hv + 0.5f * c;
        size_t off = (size_t)b * NH + h;
        hf[off] = hw;
        cf[off] = ce[h];
        __nv_bfloat16 hi = __float2bfloat16(hw);
        bhi[off] = hi;
        blo[off] = __float2bfloat16(hw - __bfloat162float(hi));
    }
}

// ---------------- step-weight prep: 32 rows per blk, unit-major, hi/lo split ----------------
// dest row = blk*32 + r, r: uu = r>>2, g = r&3; source row = g*NH + blk*8 + uu
__global__ void prep_w0_kernel(const float* __restrict__ w)
{
    int idx = blockIdx.x * 256 + threadIdx.x;
    int k = (idx & 255) * 4;
    int row = idx >> 8;
    int blk = row >> 5, r = row & 31;
    int uu = r >> 2, g = r & 3;
    int srow = g * NH + blk * 8 + uu;
    float4 v = *(const float4*)(w + (size_t)srow * NH + k);
    size_t o = (size_t)row * NH + k;
    float vv[4] = {v.x, v.y, v.z, v.w};
#pragma unroll
    for (int i = 0; i < 4; i++) {
        __nv_bfloat16 hi = __float2bfloat16(vv[i]);
        g_w0p[0][o + i] = hi;
        g_w0p[1][o + i] = __float2bfloat16(vv[i] - __bfloat162float(hi));
    }
}

__global__ void prep_w1_kernel(const float* __restrict__ wih, const float* __restrict__ whh)
{
    int idx = blockIdx.x * 256 + threadIdx.x;
    int k = (idx & 511) * 4;
    int row = idx >> 9;
    int blk = row >> 5, r = row & 31;
    int uu = r >> 2, g = r & 3;
    int srow = g * NH + blk * 8 + uu;
    const float* src = (k < NH) ? (wih + (size_t)srow * NH + k)
                                : (whh + (size_t)srow * NH + (k - NH));
    float4 v = *(const float4*)src;
    size_t o = (size_t)row * (2 * NH) + k;
    float vv[4] = {v.x, v.y, v.z, v.w};
#pragma unroll
    for (int i = 0; i < 4; i++) {
        __nv_bfloat16 hi = __float2bfloat16(vv[i]);
        g_w1p[0][o + i] = hi;
        g_w1p[1][o + i] = __float2bfloat16(vv[i] - __bfloat162float(hi));
    }
}

// ---------------- generic fp32 -> bf16 hi/lo split ----------------
__global__ void conv_split_kernel(const float* __restrict__ src,
                                  __nv_bfloat16* __restrict__ hi,
                                  __nv_bfloat16* __restrict__ lo)
{
    size_t i = ((size_t)blockIdx.x * 256 + threadIdx.x) * 4;
    float4 v = *(const float4*)(src + i);
    float vv[4] = {v.x, v.y, v.z, v.w};
#pragma unroll
    for (int j = 0; j < 4; j++) {
        __nv_bfloat16 h = __float2bfloat16(vv[j]);
        hi[i + j] = h;
        lo[i + j] = __float2bfloat16(vv[j] - __bfloat162float(h));
    }
}

// ---------------- x conversion with reorder: row m = t*64+b ----------------
__global__ void conv_x_kernel(const float* __restrict__ x)
{
    int idx = blockIdx.x * 256 + threadIdx.x;
    int kq = idx & 127;
    int m = idx >> 7;
    int t = m >> 6, b = m & 63;
    float4 v = *(const float4*)(x + ((size_t)b * NT + t) * NI + kq * 4);
    size_t o = (size_t)m * NI + kq * 4;
    float vv[4] = {v.x, v.y, v.z, v.w};
#pragma unroll
    for (int j = 0; j < 4; j++) {
        __nv_bfloat16 h = __float2bfloat16(vv[j]);
        g_xbf[0][o + j] = h;
        g_xbf[1][o + j] = __float2bfloat16(vv[j] - __bfloat162float(h));
    }
}

// ---------------- big MMA GEMM (same as R6) ----------------
#define GSTAGE 40960
#define GEMM_SMEM (2*GSTAGE)

template<int EP>
__global__ void __launch_bounds__(256) mma_gemm_kernel(
    const __nv_bfloat16* __restrict__ Ahi, const __nv_bfloat16* __restrict__ Alo,
    const __nv_bfloat16* __restrict__ Whi, const __nv_bfloat16* __restrict__ Wlo,
    const float* __restrict__ bias, const float* __restrict__ bias2,
    float* __restrict__ Cf,
    __nv_bfloat16* __restrict__ Chi, __nv_bfloat16* __restrict__ Clo,
    int N, int K, const int* __restrict__ lens)
{
    extern __shared__ char smem[];
    const uint32_t sb = smem_u32(smem);
    const int tid = threadIdx.x;
    const int lane = tid & 31, wid = tid >> 5;
    const int wm = wid & 3, wn = wid >> 2;
    const int n0 = blockIdx.x * 128;
    const int m0 = blockIdx.y * 128;
    const int KC = K >> 5;

    float acc[2][8][4] = {};

    auto issue_load = [&](int c, int stg) {
        const int k0 = c << 5;
        uint32_t base = sb + (uint32_t)stg * GSTAGE;
#pragma unroll
        for (int i = 0; i < 8; i++) {
            int s = tid + (i << 8);
            int p = s >> 9;
            int r = (s >> 2) & 127;
            int seg = s & 3;
            const __nv_bfloat16* src;
            if (p == 0)      src = Ahi + (size_t)(m0 + r) * K + k0 + seg * 8;
            else if (p == 1) src = Alo + (size_t)(m0 + r) * K + k0 + seg * 8;
            else if (p == 2) src = Whi + (size_t)(n0 + r) * K + k0 + seg * 8;
            else             src = Wlo + (size_t)(n0 + r) * K + k0 + seg * 8;
            cpa16(base + (uint32_t)(p * 10240 + r * 80 + seg * 16), src);
        }
        asm volatile("cp.async.commit_group;" ::: "memory");
    };

    issue_load(0, 0);

    const uint32_t a_base = (uint32_t)((wm * 32 + (lane & 15)) * 80 + (lane >> 4) * 16);
    const uint32_t w_base = (uint32_t)((wn * 64 + (lane & 7) + ((lane >> 4) << 3)) * 80
                                       + ((lane >> 3) & 1) * 16);

    for (int c = 0; c < KC; c++) {
        if (c + 1 < KC) {
            issue_load(c + 1, (c + 1) & 1);
            asm volatile("cp.async.wait_group 1;" ::: "memory");
        } else {
            asm volatile("cp.async.wait_group 0;" ::: "memory");
        }
        __syncthreads();

        uint32_t Ah = sb + (uint32_t)((c & 1) * GSTAGE);
        uint32_t Al = Ah + 10240, Wh = Ah + 20480, Wl = Ah + 30720;
#pragma unroll
        for (int kk = 0; kk < 2; kk++) {
            uint32_t kb = (uint32_t)kk * 32;
            uint32_t ah[2][4], al[2][4], wh[16], wl[16];
#pragma unroll
            for (int sub = 0; sub < 2; sub++) {
                ldmx4(ah[sub], Ah + a_base + sub * 16 * 80 + kb);
                ldmx4(al[sub], Al + a_base + sub * 16 * 80 + kb);
            }
#pragma unroll
            for (int q = 0; q < 4; q++) {
                ldmx4(wh + q * 4, Wh + w_base + q * 16 * 80 + kb);
                ldmx4(wl + q * 4, Wl + w_base + q * 16 * 80 + kb);
            }
#pragma unroll
            for (int sub = 0; sub < 2; sub++) {
#pragma unroll
                for (int nq = 0; nq < 8; nq++) {
                    mma16816(acc[sub][nq], ah[sub], wh + nq * 2);
                    mma16816(acc[sub][nq], al[sub], wh + nq * 2);
                    mma16816(acc[sub][nq], ah[sub], wl + nq * 2);
                }
            }
        }
        __syncthreads();
    }

#pragma unroll
    for (int sub = 0; sub < 2; sub++) {
        int r0 = m0 + wm * 32 + sub * 16 + (lane >> 2);
#pragma unroll
        for (int nq = 0; nq < 8; nq++) {
            int c0 = n0 + wn * 64 + nq * 8 + (lane & 3) * 2;
            float b0 = bias[c0], b1 = bias[c0 + 1];
            if (EP == 0) { b0 += bias2[c0]; b1 += bias2[c0 + 1]; }
#pragma unroll
            for (int half = 0; half < 2; half++) {
                int r = r0 + half * 8;
                float v0 = acc[sub][nq][half * 2]     + b0;
                float v1 = acc[sub][nq][half * 2 + 1] + b1;
                if (EP >= 1) { v0 = fmaxf(v0, 0.f); v1 = fmaxf(v1, 0.f); }
                if (EP == 2) {
                    if (lens[r >> 8] == 0) { v0 = 0.f; v1 = 0.f; }
                }
                if (EP == 1) {
                    __nv_bfloat16 h0 = __float2bfloat16(v0);
                    __nv_bfloat16 h1 = __float2bfloat16(v1);
                    __nv_bfloat162 hp; hp.x = h0; hp.y = h1;
                    __nv_bfloat162 lp;
                    lp.x = __float2bfloat16(v0 - __bfloat162float(h0));
                    lp.y = __float2bfloat16(v1 - __bfloat162float(h1));
                    *(__nv_bfloat162*)&Chi[(size_t)r * N + c0] = hp;
                    *(__nv_bfloat162*)&Clo[(size_t)r * N + c0] = lp;
                } else {
                    float2 o; o.x = v0; o.y = v1;
                    *(float2*)&Cf[(size_t)r * N + c0] = o;
                }
            }
        }
    }
}

// ---------------- persistent LSTM kernel ----------------
// 128 CTAs x 256 thr. CTA owns 8 units (32 gate rows) per layer. M=64, N=32.
// smem stage: Ahi(64x144)=9216, Alo=9216, Whi(32x144)=4608, Wlo=4608 -> 27648; x2 stages.
#define PSTG 27648
#define PERSIST_SMEM (2*PSTG)

template<int LAYER>
__device__ __forceinline__ void step_gemm(
    uint32_t sb, int tid, int lane, int wm, int wn, int blk, int ping,
    float (&d)[2][4])
{
    const int KW  = LAYER ? 2 * NH : NH;
    const int NCH = LAYER ? 32 : 16;
    const __nv_bfloat16* whi = (LAYER ? g_w1p[0] : g_w0p[0]) + (size_t)blk * 32 * KW;
    const __nv_bfloat16* wlo = (LAYER ? g_w1p[1] : g_w0p[1]) + (size_t)blk * 32 * KW;

    auto issue_load = [&](int c, int stg) {
        uint32_t base = sb + (uint32_t)stg * PSTG;
        const __nv_bfloat16 *a0, *a1;
        if (LAYER == 0) {
            a0 = g_h0bf[ping][0] + c * 64;
            a1 = g_h0bf[ping][1] + c * 64;
        } else if (c < 16) {
            a0 = g_h0in[0] + c * 64;
            a1 = g_h0in[1] + c * 64;
        } else {
            a0 = g_h1bf[ping][0] + (c - 16) * 64;
            a1 = g_h1bf[ping][1] + (c - 16) * 64;
        }
        const __nv_bfloat16* w0 = whi + c * 64;
        const __nv_bfloat16* w1 = wlo + c * 64;
#pragma unroll
        for (int i = 0; i < 6; i++) {
            int s = tid + (i << 8);      // 0..1535
            const __nv_bfloat16* src;
            uint32_t dst;
            if (s < 1024) {
                int part = s >> 9;
                int r = (s >> 3) & 63, seg = s & 7;
                src = (part ? a1 : a0) + (size_t)r * NH + seg * 8;
                dst = base + (uint32_t)(part * 9216 + r * 144 + seg * 16);
            } else {
                int part = (s >> 8) & 1;
                int r = (s >> 3) & 31, seg = s & 7;
                src = (part ? w1 : w0) + (size_t)r * KW + seg * 8;
                dst = base + (uint32_t)(18432 + part * 4608 + r * 144 + seg * 16);
            }
            cpa16(dst, src);
        }
        asm volatile("cp.async.commit_group;" ::: "memory");
    };

    issue_load(0, 0);

    const uint32_t a_off = (uint32_t)((wm * 16 + (lane & 15)) * 144 + (lane >> 4) * 16);
    const uint32_t w_off = (uint32_t)((wn * 16 + (lane & 7) + ((lane >> 4) << 3)) * 144
                                      + ((lane >> 3) & 1) * 16);

#pragma unroll 1
    for (int c = 0; c < NCH; c++) {
        if (c + 1 < NCH) {
            issue_load(c + 1, (c + 1) & 1);
            asm volatile("cp.async.wait_group 1;" ::: "memory");
        } else {
            asm volatile("cp.async.wait_group 0;" ::: "memory");
        }
        __syncthreads();

        uint32_t Ah = sb + (uint32_t)((c & 1) * PSTG);
        uint32_t Al = Ah + 9216, Wh = Ah + 18432, Wl = Ah + 23040;
#pragma unroll
        for (int kq = 0; kq < 4; kq++) {
            uint32_t kb = (uint32_t)kq * 32;
            uint32_t ah[4], al[4], wh[4], wl[4];
            ldmx4(ah, Ah + a_off + kb);
            ldmx4(al, Al + a_off + kb);
            ldmx4(wh, Wh + w_off + kb);
            ldmx4(wl, Wl + w_off + kb);
            mma16816(d[0], ah, wh); mma16816(d[1], ah, wh + 2);
            mma16816(d[0], al, wh); mma16816(d[1], al, wh + 2);
            mma16816(d[0], ah, wl); mma16816(d[1], ah, wl + 2);
        }
        __syncthreads();
    }
}

__global__ void __launch_bounds__(256) lstm_persist_kernel(
    const int* __restrict__ lens,
    const float* __restrict__ pre0,
    const float* __restrict__ bih1, const float* __restrict__ bhh1,
    float* __restrict__ out_hn, float* __restrict__ out_cn)
{
    extern __shared__ char smem[];
    const uint32_t sb = smem_u32(smem);
    const int tid = threadIdx.x;
    const int lane = tid & 31, wid = tid >> 5;
    const int wm = wid & 3, wn = wid >> 2;
    const int blk = blockIdx.x;

    const int b = wm * 16 + (lane >> 2) + ((lane & 1) << 3);
    const int rawL = lens[b];
    const int L = rawL < 1 ? 1 : rawL;

    int u[2];
    u[0] = blk * 8 + wn * 4 + 0 * 2 + ((lane & 3) >> 1);
    u[1] = blk * 8 + wn * 4 + 1 * 2 + ((lane & 3) >> 1);

    // load initial states into registers
    float c0r[2], h0r[2], c1r[2], h1r[2];
    float bs1[2][4];
#pragma unroll
    for (int nq = 0; nq < 2; nq++) {
        size_t off = (size_t)b * NH + u[nq];
        c0r[nq] = g_c0[off]; h0r[nq] = g_h0f[off];
        c1r[nq] = g_c1[off]; h1r[nq] = g_h1f[off];
#pragma unroll
        for (int g = 0; g < 4; g++)
            bs1[nq][g] = bih1[g * NH + u[nq]] + bhh1[g * NH + u[nq]];
    }

#pragma unroll 1
    for (int t = 0; t < NT; t++) {
        const int ping = t & 1;
        const bool valid = (t < L);

        // ======== phase A: layer 0 ========
        float pf[2][4];
        {
            const float* pb = pre0 + ((size_t)(t * NB + b)) * G4;
#pragma unroll
            for (int nq = 0; nq < 2; nq++)
#pragma unroll
                for (int g = 0; g < 4; g++)
                    pf[nq][g] = __ldg(pb + g * NH + u[nq]);
        }
        float d[2][4] = {};
        step_gemm<0>(sb, tid, lane, wm, wn, blk, ping, d);

#pragma unroll
        for (int nq = 0; nq < 2; nq++) {
            float s0 = (lane & 1) ? d[nq][0] : d[nq][2];
            float s1 = (lane & 1) ? d[nq][1] : d[nq][3];
            float r0 = __shfl_xor_sync(0xffffffffu, s0, 1);
            float r1 = __shfl_xor_sync(0xffffffffu, s1, 1);
            float q0, q1, q2, q3;
            if (lane & 1) { q2 = d[nq][2]; q3 = d[nq][3]; q0 = r0; q1 = r1; }
            else          { q0 = d[nq][0]; q1 = d[nq][1]; q2 = r0; q3 = r1; }

            float iv = sigf(q0 + pf[nq][0]), fv = sigf(q1 + pf[nq][1]);
            float gv = tanhft(q2 + pf[nq][2]), ov = sigf(q3 + pf[nq][3]);
            float cn = fv * c0r[nq] + iv * gv;
            float hn = ov * tanhft(cn);
            c0r[nq] = valid ? cn : c0r[nq];
            float hc = valid ? hn : h0r[nq];
            h0r[nq] = hc;
            float hin = valid ? hn : 0.f;

            size_t off = (size_t)b * NH + u[nq];
            __nv_bfloat16 hhi = __float2bfloat16(hc);
            g_h0bf[ping ^ 1][0][off] = hhi;
            g_h0bf[ping ^ 1][1][off] = __float2bfloat16(hc - __bfloat162float(hhi));
            __nv_bfloat16 ihi = __float2bfloat16(hin);
            g_h0in[0][off] = ihi;
            g_h0in[1][off] = __float2bfloat16(hin - __bfloat162float(ihi));
        }
        gbar();

        // ======== phase B: layer 1 ========
        float e[2][4] = {};
        step_gemm<1>(sb, tid, lane, wm, wn, blk, ping, e);

#pragma unroll
        for (int nq = 0; nq < 2; nq++) {
            float s0 = (lane & 1) ? e[nq][0] : e[nq][2];
            float s1 = (lane & 1) ? e[nq][1] : e[nq][3];
            float r0 = __shfl_xor_sync(0xffffffffu, s0, 1);
            float r1 = __shfl_xor_sync(0xffffffffu, s1, 1);
            float q0, q1, q2, q3;
            if (lane & 1) { q2 = e[nq][2]; q3 = e[nq][3]; q0 = r0; q1 = r1; }
            else          { q0 = e[nq][0]; q1 = e[nq][1]; q2 = r0; q3 = r1; }

            float iv = sigf(q0 + bs1[nq][0]), fv = sigf(q1 + bs1[nq][1]);
            float gv = tanhft(q2 + bs1[nq][2]), ov = sigf(q3 + bs1[nq][3]);
            float cn = fv * c1r[nq] + iv * gv;
            float hn = ov * tanhft(cn);
            c1r[nq] = valid ? cn : c1r[nq];
            float hc = valid ? hn : h1r[nq];
            h1r[nq] = hc;
            float hin = valid ? hn : 0.f;

            size_t off = (size_t)b * NH + u[nq];
            __nv_bfloat16 hhi = __float2bfloat16(hc);
            g_h1bf[ping ^ 1][0][off] = hhi;
            g_h1bf[ping ^ 1][1][off] = __float2bfloat16(hc - __bfloat162float(hhi));
            size_t om = ((size_t)b * NT + t) * NH + u[nq];
            __nv_bfloat16 ohi = __float2bfloat16(hin);
            g_loutbf[0][om] = ohi;
            g_loutbf[1][om] = __float2bfloat16(hin - __bfloat162float(ohi));
        }
        gbar();
    }

    // ---- final hn/cn (zero-length masked) ----
    const bool z = (rawL == 0);
#pragma unroll
    for (int nq = 0; nq < 2; nq++) {
        size_t off = (size_t)b * NH + u[nq];
        out_hn[off]             = z ? 0.f : h0r[nq];
        out_cn[off]             = z ? 0.f : c0r[nq];
        out_hn[NB * NH + off]   = z ? 0.f : h1r[nq];
        out_cn[NB * NH + off]   = z ? 0.f : c1r[nq];
    }
}

// ---------------- entry point ----------------
extern "C" void kernel_launch(void* const* d_in, const int* in_sizes, int n_in,
                              void* d_out, int out_size)
{
    (void)in_sizes; (void)n_in; (void)out_size;
    const float* step_input = (const float*)d_in[0];
    const float* clstm      = (const float*)d_in[1];
    const float* hidden     = (const float*)d_in[2];
    const float* cell       = (const float*)d_in[3];
    const int* lens         = (const int*)d_in[4];
    const float* w_ih0 = (const float*)d_in[5];
    const float* w_hh0 = (const float*)d_in[6];
    const float* b_ih0 = (const float*)d_in[7];
    const float* b_hh0 = (const float*)d_in[8];
    const float* w_ih1 = (const float*)d_in[9];
    const float* w_hh1 = (const float*)d_in[10];
    const float* b_ih1 = (const float*)d_in[11];
    const float* b_hh1 = (const float*)d_in[12];
    const float* w1 = (const float*)d_in[13];
    const float* b1 = (const float*)d_in[14];
    const float* w2 = (const float*)d_in[15];
    const float* b2 = (const float*)d_in[16];

    float* out = (float*)d_out;
    float* out_logits = out;
    float* out_hn = out + (size_t)NB * NT * NO;
    float* out_cn = out_hn + (size_t)NL * NB * NH;

    float* pre0p;
    cudaGetSymbolAddress((void**)&pre0p, g_pre0);
    __nv_bfloat16 *xbfp, *wih0sp, *w1sp, *w2sp, *loutp, *fc1p;
    cudaGetSymbolAddress((void**)&xbfp,   g_xbf);
    cudaGetSymbolAddress((void**)&wih0sp, g_wih0s);
    cudaGetSymbolAddress((void**)&w1sp,   g_w1s);
    cudaGetSymbolAddress((void**)&w2sp,   g_w2s);
    cudaGetSymbolAddress((void**)&loutp,  g_loutbf);
    cudaGetSymbolAddress((void**)&fc1p,   g_fc1bf);
    const size_t XSZ = (size_t)MROWS * NI;
    const size_t WIH0SZ = (size_t)G4 * NI;
    const size_t W1SZ = (size_t)NH * NH;
    const size_t W2SZ = (size_t)NO * NH;
    const size_t LSZ = (size_t)MROWS * NH;

    cudaFuncSetAttribute(lstm_persist_kernel, cudaFuncAttributeMaxDynamicSharedMemorySize, PERSIST_SMEM);
    cudaFuncSetAttribute(mma_gemm_kernel<0>, cudaFuncAttributeMaxDynamicSharedMemorySize, GEMM_SMEM);
    cudaFuncSetAttribute(mma_gemm_kernel<1>, cudaFuncAttributeMaxDynamicSharedMemorySize, GEMM_SMEM);
    cudaFuncSetAttribute(mma_gemm_kernel<2>, cudaFuncAttributeMaxDynamicSharedMemorySize, GEMM_SMEM);

    // 1) init state + weight/input prep
    init_state_kernel<<<NL * NB, 256>>>(clstm, hidden, cell, lens);
    prep_w0_kernel<<<4096, 256>>>(w_hh0);
    prep_w1_kernel<<<8192, 256>>>(w_ih1, w_hh1);
    conv_x_kernel<<<8192, 256>>>(step_input);
    conv_split_kernel<<<(int)(WIH0SZ / 1024), 256>>>(w_ih0, wih0sp, wih0sp + WIH0SZ);
    conv_split_kernel<<<(int)(W1SZ / 1024), 256>>>(w1, w1sp, w1sp + W1SZ);
    conv_split_kernel<<<(int)(W2SZ / 1024), 256>>>(w2, w2sp, w2sp + W2SZ);

    // 2) pre0 = x @ Wih0^T + b_ih0 + b_hh0
    mma_gemm_kernel<0><<<dim3(G4 / 128, MROWS / 128), 256, GEMM_SMEM>>>(
        xbfp, xbfp + XSZ, wih0sp, wih0sp + WIH0SZ, b_ih0, b_hh0,
        pre0p, nullptr, nullptr, G4, NI, nullptr);

    // 3) the whole 256-step LSTM in ONE persistent kernel
    lstm_persist_kernel<<<NCTA, 256, PERSIST_SMEM>>>(lens, pre0p, b_ih1, b_hh1, out_hn, out_cn);

    // 4) FC1: relu(lstm_out @ w1^T + b1) -> hi/lo bf16
    mma_gemm_kernel<1><<<dim3(NH / 128, MROWS / 128), 256, GEMM_SMEM>>>(
        loutp, loutp + LSZ, w1sp, w1sp + W1SZ, b1, nullptr,
        nullptr, fc1p, fc1p + LSZ, NH, NH, nullptr);

    // 5) FC2: relu(fc1 @ w2^T + b2), zero-length masked, fp32 out
    mma_gemm_kernel<2><<<dim3(NO / 128, MROWS / 128), 256, GEMM_SMEM>>>(
        fc1p, fc1p + LSZ, w2sp, w2sp + W2SZ, b2, nullptr,
        out_logits, nullptr, nullptr, NO, NH, lens);
}